// round 6
// baseline (speedup 1.0000x reference)
#include <cuda_runtime.h>
#include <cuda_bf16.h>
#include <cstdint>

#define N_NODES  50000
#define N_EDGES  400000
#define N_GRAPHS 500
#define N_FEAT   4
#define EMB      200
#define HID      128

// ---------------- device scratch (no runtime allocation allowed) ----------
__device__ float g_bufA[(size_t)N_NODES * EMB];
__device__ float g_bufB[(size_t)N_NODES * EMB];
__device__ float g_hw  [(size_t)N_NODES * EMB];
__device__ float g_dinv[N_NODES];
__device__ int   g_deg [N_NODES];
__device__ int   g_off [N_NODES + 1];
__device__ int   g_cur [N_NODES];
__device__ int   g_csr_src [N_EDGES];
__device__ float g_csr_coef[N_EDGES];
__device__ int   g_flag_ei;   // 1 if edge_index is int64, 0 if int32
__device__ int   g_flag_bi;   // 1 if batch_index is int64, 0 if int32
__device__ float g_pool[N_GRAPHS * EMB];
__device__ int   g_gcnt[N_GRAPHS];
__device__ int   g_goff[N_GRAPHS];

// ---------------- dtype detection ----------------------------------------
// int64 little-endian values in [0, 50000) have zero high words.
// Edge ids are random -> 16 odd int32 slots all zero <=> int64.
// batch_index is sorted (starts with zeros), so sample mid-array where
// int32 values are ~400 (nonzero), while int64 high words are still 0.
__global__ void detect_kernel(const void* ei, const void* bi) {
    if (threadIdx.x == 0 && blockIdx.x == 0) {
        const int* e32 = (const int*)ei;
        int all0 = 1;
        for (int i = 0; i < 16; i++) if (e32[2 * i + 1] != 0) all0 = 0;
        g_flag_ei = all0;
        const int* b32 = (const int*)bi;
        int all0b = 1;
        for (int i = 0; i < 16; i++) if (b32[2 * (20000 + i) + 1] != 0) all0b = 0;
        g_flag_bi = all0b;
    }
}

__device__ __forceinline__ int ld_idx(const void* p, long long i, int is64) {
    if (is64) return (int)((const long long*)p)[i];
    return ((const int*)p)[i];
}

// ---------------- graph preprocessing -------------------------------------
__global__ void init_kernel() {
    int i = blockIdx.x * blockDim.x + threadIdx.x;
    if (i < N_NODES) { g_deg[i] = 0; g_cur[i] = 0; }
    if (i < N_GRAPHS) g_gcnt[i] = 0;
}

__global__ void count_deg_kernel(const void* ei) {
    int e = blockIdx.x * blockDim.x + threadIdx.x;
    if (e >= N_EDGES) return;
    int is64 = g_flag_ei;
    int d = ld_idx(ei, (long long)N_EDGES + e, is64);
    atomicAdd(&g_deg[d], 1);
}

// single-block exclusive scan over 50000 degree counts
__global__ void scan_off_kernel() {
    __shared__ int s[1024];
    int t = threadIdx.x;
    const int CH = (N_NODES + 1023) / 1024;  // 49
    int start = t * CH;
    int sum = 0;
    for (int i = 0; i < CH; i++) {
        int k = start + i;
        if (k < N_NODES) sum += g_deg[k];
    }
    s[t] = sum;
    __syncthreads();
    for (int d = 1; d < 1024; d <<= 1) {
        int v = 0;
        if (t >= d) v = s[t - d];
        __syncthreads();
        if (t >= d) s[t] += v;
        __syncthreads();
    }
    int run = (t == 0) ? 0 : s[t - 1];
    for (int i = 0; i < CH; i++) {
        int k = start + i;
        if (k < N_NODES) { g_off[k] = run; run += g_deg[k]; }
    }
    if (t == 1023) g_off[N_NODES] = s[1023];
}

__global__ void dinv_kernel() {
    int i = blockIdx.x * blockDim.x + threadIdx.x;
    if (i < N_NODES) g_dinv[i] = rsqrtf((float)(g_deg[i] + 1));  // +1 self-loop
}

__global__ void scatter_kernel(const void* ei) {
    int e = blockIdx.x * blockDim.x + threadIdx.x;
    if (e >= N_EDGES) return;
    int is64 = g_flag_ei;
    int s = ld_idx(ei, e, is64);
    int d = ld_idx(ei, (long long)N_EDGES + e, is64);
    int p = g_off[d] + atomicAdd(&g_cur[d], 1);
    g_csr_src[p]  = s;
    g_csr_coef[p] = g_dinv[s] * g_dinv[d];
}

__global__ void count_batch_kernel(const void* bi) {
    int i = blockIdx.x * blockDim.x + threadIdx.x;
    if (i >= N_NODES) return;
    int b = ld_idx(bi, i, g_flag_bi);
    atomicAdd(&g_gcnt[b], 1);
}

__global__ void scan_goff_kernel() {
    __shared__ int s[512];
    int t = threadIdx.x;
    s[t] = (t < N_GRAPHS) ? g_gcnt[t] : 0;
    __syncthreads();
    for (int d = 1; d < 512; d <<= 1) {
        int v = 0;
        if (t >= d) v = s[t - d];
        __syncthreads();
        if (t >= d) s[t] += v;
        __syncthreads();
    }
    if (t < N_GRAPHS) g_goff[t] = (t == 0) ? 0 : s[t - 1];
}

// ---------------- GEMMs ----------------------------------------------------
// layer 0: [50000,4] @ [4,200] — thread per output element
__global__ void gemm0_kernel(const float* __restrict__ x,
                             const float* __restrict__ W0,
                             float* __restrict__ out) {
    int idx = blockIdx.x * blockDim.x + threadIdx.x;
    if (idx >= N_NODES * EMB) return;
    int i = idx / EMB, f = idx - i * EMB;
    const float* xr = x + i * 4;
    float s = xr[0] * __ldg(&W0[f])
            + xr[1] * __ldg(&W0[EMB + f])
            + xr[2] * __ldg(&W0[2 * EMB + f])
            + xr[3] * __ldg(&W0[3 * EMB + f]);
    out[idx] = s;
}

// layers 1-3: [50000,200] @ [200,200]. 32-row tile in smem, thread = 1 col,
// float4 smem broadcasts -> FFMA-pipe bound.
#define GEMM_ROWS 32
__global__ __launch_bounds__(256) void gemm200_kernel(
    const float* __restrict__ h, const float* __restrict__ W,
    float* __restrict__ out) {
    __shared__ float sh[GEMM_ROWS * EMB];
    int row0 = blockIdx.x * GEMM_ROWS;
    int t = threadIdx.x;

    for (int idx = t; idx < GEMM_ROWS * EMB; idx += 256) {
        int r = idx / EMB;
        int gi = row0 + r;
        sh[idx] = (gi < N_NODES) ? h[(size_t)gi * EMB + (idx - r * EMB)] : 0.f;
    }
    __syncthreads();

    if (t < EMB) {
        float acc[GEMM_ROWS];
#pragma unroll
        for (int r = 0; r < GEMM_ROWS; r++) acc[r] = 0.f;

        for (int k = 0; k < EMB; k += 4) {
            float w0 = __ldg(&W[(k + 0) * EMB + t]);
            float w1 = __ldg(&W[(k + 1) * EMB + t]);
            float w2 = __ldg(&W[(k + 2) * EMB + t]);
            float w3 = __ldg(&W[(k + 3) * EMB + t]);
#pragma unroll
            for (int r = 0; r < GEMM_ROWS; r++) {
                float4 hv = *reinterpret_cast<const float4*>(&sh[r * EMB + k]);
                acc[r] += hv.x * w0;
                acc[r] += hv.y * w1;
                acc[r] += hv.z * w2;
                acc[r] += hv.w * w3;
            }
        }
#pragma unroll
        for (int r = 0; r < GEMM_ROWS; r++) {
            int gi = row0 + r;
            if (gi < N_NODES) out[(size_t)gi * EMB + t] = acc[r];
        }
    }
}

// ---------------- edge aggregation (gather, warp per dst node) -------------
// out[i] = leaky( sum_{e in CSR(i)} coef*hw[src] + dinv[i]^2*hw[i] + b )
__global__ __launch_bounds__(256) void aggregate_kernel(
    const float* __restrict__ hw, const float* __restrict__ b,
    float* __restrict__ out) {
    int warp = (blockIdx.x * blockDim.x + threadIdx.x) >> 5;
    int lane = threadIdx.x & 31;
    if (warp >= N_NODES) return;
    int i = warp;

    float dv = g_dinv[i];
    float selfc = dv * dv;

    const float4* hi4 = reinterpret_cast<const float4*>(hw + (size_t)i * EMB);
    float4 a0 = make_float4(0.f, 0.f, 0.f, 0.f);
    float4 a1 = a0;
    {
        float4 v0 = hi4[lane];
        a0.x = selfc * v0.x; a0.y = selfc * v0.y; a0.z = selfc * v0.z; a0.w = selfc * v0.w;
        if (lane < 18) {
            float4 v1 = hi4[32 + lane];
            a1.x = selfc * v1.x; a1.y = selfc * v1.y; a1.z = selfc * v1.z; a1.w = selfc * v1.w;
        }
    }

    int e0 = g_off[i], e1 = g_off[i + 1];
    for (int e = e0; e < e1; e++) {
        int   s = g_csr_src[e];
        float c = g_csr_coef[e];
        const float4* hs4 = reinterpret_cast<const float4*>(hw + (size_t)s * EMB);
        float4 v0 = hs4[lane];
        a0.x += c * v0.x; a0.y += c * v0.y; a0.z += c * v0.z; a0.w += c * v0.w;
        if (lane < 18) {
            float4 v1 = hs4[32 + lane];
            a1.x += c * v1.x; a1.y += c * v1.y; a1.z += c * v1.z; a1.w += c * v1.w;
        }
    }

    const float4* b4 = reinterpret_cast<const float4*>(b);
    float4* o4 = reinterpret_cast<float4*>(out + (size_t)i * EMB);
    {
        float4 bb = b4[lane];
        float4 v;
        v.x = a0.x + bb.x; v.y = a0.y + bb.y; v.z = a0.z + bb.z; v.w = a0.w + bb.w;
        v.x = v.x > 0.f ? v.x : 0.01f * v.x;
        v.y = v.y > 0.f ? v.y : 0.01f * v.y;
        v.z = v.z > 0.f ? v.z : 0.01f * v.z;
        v.w = v.w > 0.f ? v.w : 0.01f * v.w;
        o4[lane] = v;
        if (lane < 18) {
            float4 bb1 = b4[32 + lane];
            float4 w;
            w.x = a1.x + bb1.x; w.y = a1.y + bb1.y; w.z = a1.z + bb1.z; w.w = a1.w + bb1.w;
            w.x = w.x > 0.f ? w.x : 0.01f * w.x;
            w.y = w.y > 0.f ? w.y : 0.01f * w.y;
            w.z = w.z > 0.f ? w.z : 0.01f * w.z;
            w.w = w.w > 0.f ? w.w : 0.01f * w.w;
            o4[32 + lane] = w;
        }
    }
}

// ---------------- pooling + MLP head ---------------------------------------
__global__ void pool_kernel(const float* __restrict__ h) {
    int g = blockIdx.x;
    int t = threadIdx.x;
    if (t >= EMB) return;
    int r0 = g_goff[g];
    int n = g_gcnt[g];
    float s = 0.f;
    for (int j = 0; j < n; j++) s += h[(size_t)(r0 + j) * EMB + t];
    g_pool[g * EMB + t] = s / fmaxf((float)n, 1.0f);
}

__global__ __launch_bounds__(HID) void mlp_kernel(
    const float* __restrict__ xs,
    const float* __restrict__ Wl1, const float* __restrict__ bl1,
    const float* __restrict__ Wl2, const float* __restrict__ bl2,
    float* __restrict__ out) {
    int g = blockIdx.x;
    int t = threadIdx.x;  // 128
    __shared__ float gv[EMB + N_FEAT];
    __shared__ float red[HID];

    for (int k = t; k < EMB; k += HID) gv[k] = g_pool[g * EMB + k];
    if (t < N_FEAT) gv[EMB + t] = xs[g * N_FEAT + t];
    __syncthreads();

    float acc = bl1[t];
    for (int k = 0; k < EMB + N_FEAT; k++) acc += gv[k] * Wl1[k * HID + t];
    acc = acc > 0.f ? acc : 0.01f * acc;
    red[t] = acc * Wl2[t];
    __syncthreads();
    for (int s = HID / 2; s > 0; s >>= 1) {
        if (t < s) red[t] += red[t + s];
        __syncthreads();
    }
    if (t == 0) out[g] = red[0] + bl2[0];
}

// ---------------- launcher --------------------------------------------------
extern "C" void kernel_launch(void* const* d_in, const int* in_sizes, int n_in,
                              void* d_out, int out_size) {
    const float* x        = (const float*)d_in[0];
    const void*  ei       = d_in[1];
    const float* x_scalar = (const float*)d_in[2];
    const void*  bi       = d_in[3];
    const float* W0  = (const float*)d_in[4];
    const float* b0  = (const float*)d_in[5];
    const float* W1  = (const float*)d_in[6];
    const float* b1  = (const float*)d_in[7];
    const float* W2  = (const float*)d_in[8];
    const float* b2  = (const float*)d_in[9];
    const float* W3  = (const float*)d_in[10];
    const float* b3  = (const float*)d_in[11];
    const float* Wl1 = (const float*)d_in[12];
    const float* bl1 = (const float*)d_in[13];
    const float* Wl2 = (const float*)d_in[14];
    const float* bl2 = (const float*)d_in[15];
    float* out = (float*)d_out;

    float *bufA, *bufB, *hw;
    cudaGetSymbolAddress((void**)&bufA, g_bufA);
    cudaGetSymbolAddress((void**)&bufB, g_bufB);
    cudaGetSymbolAddress((void**)&hw,   g_hw);

    const int TB = 256;
    int gridN  = (N_NODES + TB - 1) / TB;              // 196
    int gridE  = (N_EDGES + TB - 1) / TB;              // 1563
    int gridNE = (N_NODES * EMB + TB - 1) / TB;        // 39063
    int gridAg = (N_NODES * 32 + TB - 1) / TB;         // 6250 (warp per node)
    int gridGm = (N_NODES + GEMM_ROWS - 1) / GEMM_ROWS;

    // preprocessing (graph structure, once per launch)
    detect_kernel<<<1, 32>>>(ei, bi);
    init_kernel<<<gridN, TB>>>();
    count_deg_kernel<<<gridE, TB>>>(ei);
    scan_off_kernel<<<1, 1024>>>();
    dinv_kernel<<<gridN, TB>>>();
    scatter_kernel<<<gridE, TB>>>(ei);
    count_batch_kernel<<<gridN, TB>>>(bi);
    scan_goff_kernel<<<1, 512>>>();

    // layer 0
    gemm0_kernel<<<gridNE, TB>>>(x, W0, hw);
    aggregate_kernel<<<gridAg, TB>>>(hw, b0, bufA);
    // layer 1
    gemm200_kernel<<<gridGm, TB>>>(bufA, W1, hw);
    aggregate_kernel<<<gridAg, TB>>>(hw, b1, bufB);
    // layer 2
    gemm200_kernel<<<gridGm, TB>>>(bufB, W2, hw);
    aggregate_kernel<<<gridAg, TB>>>(hw, b2, bufA);
    // layer 3
    gemm200_kernel<<<gridGm, TB>>>(bufA, W3, hw);
    aggregate_kernel<<<gridAg, TB>>>(hw, b3, bufB);

    // pool + MLP head
    pool_kernel<<<N_GRAPHS, 256>>>(bufB);
    mlp_kernel<<<N_GRAPHS, HID>>>(x_scalar, Wl1, bl1, Wl2, bl2, out);
}

// round 7
// speedup vs baseline: 1.3121x; 1.3121x over previous
#include <cuda_runtime.h>
#include <cuda_bf16.h>
#include <cstdint>

#define N_NODES  50000
#define N_EDGES  400000
#define N_GRAPHS 500
#define N_FEAT   4
#define EMB      200
#define HID      128

// ---------------- device scratch (no runtime allocation allowed) ----------
__device__ float g_bufA[(size_t)N_NODES * EMB];
__device__ float g_bufB[(size_t)N_NODES * EMB];
__device__ float g_hw  [(size_t)N_NODES * EMB];
__device__ float g_dinv[N_NODES];
__device__ int   g_deg [N_NODES];
__device__ int   g_off [N_NODES + 1];
__device__ int   g_cur [N_NODES];
__device__ int   g_csr_src [N_EDGES];
__device__ float g_csr_coef[N_EDGES];
__device__ int   g_flag_ei;   // 1 if edge_index is int64, 0 if int32
__device__ int   g_flag_bi;   // 1 if batch_index is int64, 0 if int32
__device__ float g_pool[N_GRAPHS * EMB];
__device__ int   g_gcnt[N_GRAPHS];
__device__ int   g_goff[N_GRAPHS];
__device__ int   g_part [64];
__device__ int   g_pscan[64];

// ---------------- dtype detection ----------------------------------------
__global__ void detect_kernel(const void* ei, const void* bi) {
    if (threadIdx.x == 0 && blockIdx.x == 0) {
        const int* e32 = (const int*)ei;
        int all0 = 1;
        for (int i = 0; i < 16; i++) if (e32[2 * i + 1] != 0) all0 = 0;
        g_flag_ei = all0;
        const int* b32 = (const int*)bi;
        int all0b = 1;
        for (int i = 0; i < 16; i++) if (b32[2 * (20000 + i) + 1] != 0) all0b = 0;
        g_flag_bi = all0b;
    }
}

__device__ __forceinline__ int ld_idx(const void* p, long long i, int is64) {
    if (is64) return (int)((const long long*)p)[i];
    return ((const int*)p)[i];
}

// ---------------- graph preprocessing -------------------------------------
__global__ void init_kernel() {
    int i = blockIdx.x * blockDim.x + threadIdx.x;
    if (i < N_NODES) { g_deg[i] = 0; g_cur[i] = 0; }
    if (i < N_GRAPHS) g_gcnt[i] = 0;
}

__global__ void count_deg_kernel(const void* ei) {
    int e = blockIdx.x * blockDim.x + threadIdx.x;
    if (e >= N_EDGES) return;
    int is64 = g_flag_ei;
    int d = ld_idx(ei, (long long)N_EDGES + e, is64);
    atomicAdd(&g_deg[d], 1);
}

// ---- two-level coalesced scan of g_deg -> g_off (exclusive) --------------
#define SCAN_B 1024
#define SCAN_NB ((N_NODES + SCAN_B - 1) / SCAN_B)   // 49

__global__ void scan_part_kernel() {
    __shared__ int ws[32];
    int i = blockIdx.x * SCAN_B + threadIdx.x;
    int v = (i < N_NODES) ? g_deg[i] : 0;
#pragma unroll
    for (int d = 16; d; d >>= 1) v += __shfl_down_sync(0xffffffffu, v, d);
    if ((threadIdx.x & 31) == 0) ws[threadIdx.x >> 5] = v;
    __syncthreads();
    if (threadIdx.x < 32) {
        int s = ws[threadIdx.x];
#pragma unroll
        for (int d = 16; d; d >>= 1) s += __shfl_down_sync(0xffffffffu, s, d);
        if (threadIdx.x == 0) g_part[blockIdx.x] = s;
    }
}

__global__ void scan_top_kernel() {
    __shared__ int s[64];
    int t = threadIdx.x;
    int v = (t < SCAN_NB) ? g_part[t] : 0;
    s[t] = v;
    __syncthreads();
    for (int d = 1; d < 64; d <<= 1) {
        int u = 0;
        if (t >= d) u = s[t - d];
        __syncthreads();
        s[t] += u;
        __syncthreads();
    }
    if (t < SCAN_NB) g_pscan[t] = s[t] - v;  // exclusive block offsets
    if (t == 0) g_off[N_NODES] = N_EDGES;
}

__global__ void scan_final_kernel() {
    __shared__ int wsum[32];
    int tid = threadIdx.x, lane = tid & 31, wid = tid >> 5;
    int i = blockIdx.x * SCAN_B + tid;
    int v = (i < N_NODES) ? g_deg[i] : 0;
    int inc = v;
#pragma unroll
    for (int d = 1; d < 32; d <<= 1) {
        int u = __shfl_up_sync(0xffffffffu, inc, d);
        if (lane >= d) inc += u;
    }
    if (lane == 31) wsum[wid] = inc;
    __syncthreads();
    if (wid == 0) {
        int s = wsum[lane];
        int si = s;
#pragma unroll
        for (int d = 1; d < 32; d <<= 1) {
            int u = __shfl_up_sync(0xffffffffu, si, d);
            if (lane >= d) si += u;
        }
        wsum[lane] = si - s;
    }
    __syncthreads();
    if (i < N_NODES) {
        g_off[i]  = g_pscan[blockIdx.x] + wsum[wid] + (inc - v);
        g_dinv[i] = rsqrtf((float)(v + 1));   // +1 self-loop
    }
}

__global__ void scatter_kernel(const void* ei) {
    int e = blockIdx.x * blockDim.x + threadIdx.x;
    if (e >= N_EDGES) return;
    int is64 = g_flag_ei;
    int s = ld_idx(ei, e, is64);
    int d = ld_idx(ei, (long long)N_EDGES + e, is64);
    int p = g_off[d] + atomicAdd(&g_cur[d], 1);
    g_csr_src[p]  = s;
    g_csr_coef[p] = g_dinv[s] * g_dinv[d];
}

__global__ void count_batch_kernel(const void* bi) {
    int i = blockIdx.x * blockDim.x + threadIdx.x;
    if (i >= N_NODES) return;
    int b = ld_idx(bi, i, g_flag_bi);
    atomicAdd(&g_gcnt[b], 1);
}

__global__ void scan_goff_kernel() {
    __shared__ int s[512];
    int t = threadIdx.x;
    s[t] = (t < N_GRAPHS) ? g_gcnt[t] : 0;
    __syncthreads();
    for (int d = 1; d < 512; d <<= 1) {
        int v = 0;
        if (t >= d) v = s[t - d];
        __syncthreads();
        if (t >= d) s[t] += v;
        __syncthreads();
    }
    if (t < N_GRAPHS) g_goff[t] = (t == 0) ? 0 : s[t - 1];
}

// ---------------- GEMMs ----------------------------------------------------
// layer 0: [50000,4] @ [4,200] — thread per output element (memory bound)
__global__ void gemm0_kernel(const float* __restrict__ x,
                             const float* __restrict__ W0,
                             float* __restrict__ out) {
    int idx = blockIdx.x * blockDim.x + threadIdx.x;
    if (idx >= N_NODES * EMB) return;
    int i = idx / EMB, f = idx - i * EMB;
    const float* xr = x + i * 4;
    float s = xr[0] * __ldg(&W0[f])
            + xr[1] * __ldg(&W0[EMB + f])
            + xr[2] * __ldg(&W0[2 * EMB + f])
            + xr[3] * __ldg(&W0[3 * EMB + f]);
    out[idx] = s;
}

// layers 1-3: tf32x3 tensor-core GEMM, [50000,200] @ [200,200]
// block tile M=64, N=208 (padded, stores masked to 200), K-step 8,
// double-buffered smem, 8 warps = 4(M) x 2(N), warp tile 16 x 104 (13 n-tiles)
#define BM    64
#define BSTR  216   // B smem stride (216 mod 32 = 24 -> conflict-free b-frags)

__device__ __forceinline__ float cvt_tf32(float x) {
    uint32_t u;
    asm("cvt.rna.tf32.f32 %0, %1;" : "=r"(u) : "f"(x));
    return __uint_as_float(u);
}

#define MMA_TF32(d, a0, a1, a2, a3, b0, b1)                                  \
    asm volatile("mma.sync.aligned.m16n8k8.row.col.f32.tf32.tf32.f32 "      \
                 "{%0,%1,%2,%3}, {%4,%5,%6,%7}, {%8,%9}, {%0,%1,%2,%3};"    \
                 : "+f"((d)[0]), "+f"((d)[1]), "+f"((d)[2]), "+f"((d)[3])   \
                 : "r"(a0), "r"(a1), "r"(a2), "r"(a3), "r"(b0), "r"(b1))

__global__ __launch_bounds__(256) void gemm_tf32_kernel(
    const float* __restrict__ h, const float* __restrict__ W,
    float* __restrict__ out) {
    __shared__ float sAh[2][BM * 8];
    __shared__ float sAl[2][BM * 8];
    __shared__ float sBh[2][8 * BSTR];
    __shared__ float sBl[2][8 * BSTR];

    int tid  = threadIdx.x;
    int lane = tid & 31, warp = tid >> 5;
    int wm = warp >> 1;       // 0..3 (M)
    int wn = warp & 1;        // 0..1 (N)
    int row0 = blockIdx.x * BM;
    int gid = lane >> 2;      // 0..7
    int tig = lane & 3;       // 0..3

    float acc[13][4];
#pragma unroll
    for (int t = 0; t < 13; t++) {
        acc[t][0] = 0.f; acc[t][1] = 0.f; acc[t][2] = 0.f; acc[t][3] = 0.f;
    }

    float ra[2];
    float rb[7];

    auto FETCH = [&](int k0) {
#pragma unroll
        for (int i = 0; i < 2; i++) {
            int idx = tid + i * 256;              // 0..511
            int r = idx >> 3, c = idx & 7;
            int gr = row0 + r;
            ra[i] = (gr < N_NODES) ? __ldg(&h[(size_t)gr * EMB + k0 + c]) : 0.f;
        }
#pragma unroll
        for (int i = 0; i < 7; i++) {
            int idx = tid + i * 256;              // 0..1791
            rb[i] = 0.f;
            if (idx < 8 * 208) {
                int r = idx / 208, c = idx - r * 208;
                if (c < EMB) rb[i] = __ldg(&W[(size_t)(k0 + r) * EMB + c]);
            }
        }
    };
    auto STORE = [&](int buf) {
#pragma unroll
        for (int i = 0; i < 2; i++) {
            int idx = tid + i * 256;
            float hi = cvt_tf32(ra[i]);
            sAh[buf][idx] = hi;
            sAl[buf][idx] = cvt_tf32(ra[i] - hi);
        }
#pragma unroll
        for (int i = 0; i < 7; i++) {
            int idx = tid + i * 256;
            if (idx < 8 * 208) {
                int r = idx / 208, c = idx - r * 208;
                float hi = cvt_tf32(rb[i]);
                sBh[buf][r * BSTR + c] = hi;
                sBl[buf][r * BSTR + c] = cvt_tf32(rb[i] - hi);
            }
        }
    };

    FETCH(0);
    STORE(0);
    __syncthreads();

    int arow = wm * 16 + gid;
#pragma unroll 1
    for (int ks = 0; ks < 25; ks++) {
        int cur = ks & 1;
        if (ks < 24) FETCH((ks + 1) * 8);

        uint32_t ah0 = __float_as_uint(sAh[cur][arow * 8 + tig]);
        uint32_t ah1 = __float_as_uint(sAh[cur][(arow + 8) * 8 + tig]);
        uint32_t ah2 = __float_as_uint(sAh[cur][arow * 8 + tig + 4]);
        uint32_t ah3 = __float_as_uint(sAh[cur][(arow + 8) * 8 + tig + 4]);
        uint32_t al0 = __float_as_uint(sAl[cur][arow * 8 + tig]);
        uint32_t al1 = __float_as_uint(sAl[cur][(arow + 8) * 8 + tig]);
        uint32_t al2 = __float_as_uint(sAl[cur][arow * 8 + tig + 4]);
        uint32_t al3 = __float_as_uint(sAl[cur][(arow + 8) * 8 + tig + 4]);

#pragma unroll
        for (int t = 0; t < 13; t++) {
            int n = wn * 104 + t * 8 + gid;
            uint32_t bh0 = __float_as_uint(sBh[cur][tig * BSTR + n]);
            uint32_t bh1 = __float_as_uint(sBh[cur][(tig + 4) * BSTR + n]);
            uint32_t bl0 = __float_as_uint(sBl[cur][tig * BSTR + n]);
            uint32_t bl1 = __float_as_uint(sBl[cur][(tig + 4) * BSTR + n]);
            MMA_TF32(acc[t], ah0, ah1, ah2, ah3, bh0, bh1);
            MMA_TF32(acc[t], al0, al1, al2, al3, bh0, bh1);
            MMA_TF32(acc[t], ah0, ah1, ah2, ah3, bl0, bl1);
        }

        if (ks < 24) STORE(cur ^ 1);
        __syncthreads();
    }

    // store C (float2 per fragment row, mask n >= 200 and row >= N_NODES)
#pragma unroll
    for (int t = 0; t < 13; t++) {
        int n = wn * 104 + t * 8 + 2 * tig;
        if (n >= EMB) continue;
        int r = row0 + wm * 16 + gid;
        if (r < N_NODES)
            *reinterpret_cast<float2*>(&out[(size_t)r * EMB + n]) =
                make_float2(acc[t][0], acc[t][1]);
        if (r + 8 < N_NODES)
            *reinterpret_cast<float2*>(&out[(size_t)(r + 8) * EMB + n]) =
                make_float2(acc[t][2], acc[t][3]);
    }
}

// ---------------- edge aggregation (gather, warp per dst node) -------------
__global__ __launch_bounds__(256) void aggregate_kernel(
    const float* __restrict__ hw, const float* __restrict__ b,
    float* __restrict__ out) {
    int warp = (blockIdx.x * blockDim.x + threadIdx.x) >> 5;
    int lane = threadIdx.x & 31;
    if (warp >= N_NODES) return;
    int i = warp;

    float dv = g_dinv[i];
    float selfc = dv * dv;

    const float4* hi4 = reinterpret_cast<const float4*>(hw + (size_t)i * EMB);
    float4 a0 = make_float4(0.f, 0.f, 0.f, 0.f);
    float4 a1 = a0;
    {
        float4 v0 = hi4[lane];
        a0.x = selfc * v0.x; a0.y = selfc * v0.y; a0.z = selfc * v0.z; a0.w = selfc * v0.w;
        if (lane < 18) {
            float4 v1 = hi4[32 + lane];
            a1.x = selfc * v1.x; a1.y = selfc * v1.y; a1.z = selfc * v1.z; a1.w = selfc * v1.w;
        }
    }

    int e0 = g_off[i], e1 = g_off[i + 1];
    for (int e = e0; e < e1; e++) {
        int   s = g_csr_src[e];
        float c = g_csr_coef[e];
        const float4* hs4 = reinterpret_cast<const float4*>(hw + (size_t)s * EMB);
        float4 v0 = hs4[lane];
        a0.x += c * v0.x; a0.y += c * v0.y; a0.z += c * v0.z; a0.w += c * v0.w;
        if (lane < 18) {
            float4 v1 = hs4[32 + lane];
            a1.x += c * v1.x; a1.y += c * v1.y; a1.z += c * v1.z; a1.w += c * v1.w;
        }
    }

    const float4* b4 = reinterpret_cast<const float4*>(b);
    float4* o4 = reinterpret_cast<float4*>(out + (size_t)i * EMB);
    {
        float4 bb = b4[lane];
        float4 v;
        v.x = a0.x + bb.x; v.y = a0.y + bb.y; v.z = a0.z + bb.z; v.w = a0.w + bb.w;
        v.x = v.x > 0.f ? v.x : 0.01f * v.x;
        v.y = v.y > 0.f ? v.y : 0.01f * v.y;
        v.z = v.z > 0.f ? v.z : 0.01f * v.z;
        v.w = v.w > 0.f ? v.w : 0.01f * v.w;
        o4[lane] = v;
        if (lane < 18) {
            float4 bb1 = b4[32 + lane];
            float4 w;
            w.x = a1.x + bb1.x; w.y = a1.y + bb1.y; w.z = a1.z + bb1.z; w.w = a1.w + bb1.w;
            w.x = w.x > 0.f ? w.x : 0.01f * w.x;
            w.y = w.y > 0.f ? w.y : 0.01f * w.y;
            w.z = w.z > 0.f ? w.z : 0.01f * w.z;
            w.w = w.w > 0.f ? w.w : 0.01f * w.w;
            o4[32 + lane] = w;
        }
    }
}

// ---------------- pooling + MLP head ---------------------------------------
__global__ void pool_kernel(const float* __restrict__ h) {
    int g = blockIdx.x;
    int t = threadIdx.x;
    if (t >= EMB) return;
    int r0 = g_goff[g];
    int n = g_gcnt[g];
    float s = 0.f;
    for (int j = 0; j < n; j++) s += h[(size_t)(r0 + j) * EMB + t];
    g_pool[g * EMB + t] = s / fmaxf((float)n, 1.0f);
}

__global__ __launch_bounds__(HID) void mlp_kernel(
    const float* __restrict__ xs,
    const float* __restrict__ Wl1, const float* __restrict__ bl1,
    const float* __restrict__ Wl2, const float* __restrict__ bl2,
    float* __restrict__ out) {
    int g = blockIdx.x;
    int t = threadIdx.x;  // 128
    __shared__ float gv[EMB + N_FEAT];
    __shared__ float red[HID];

    for (int k = t; k < EMB; k += HID) gv[k] = g_pool[g * EMB + k];
    if (t < N_FEAT) gv[EMB + t] = xs[g * N_FEAT + t];
    __syncthreads();

    float acc = bl1[t];
    for (int k = 0; k < EMB + N_FEAT; k++) acc += gv[k] * Wl1[k * HID + t];
    acc = acc > 0.f ? acc : 0.01f * acc;
    red[t] = acc * Wl2[t];
    __syncthreads();
    for (int s = HID / 2; s > 0; s >>= 1) {
        if (t < s) red[t] += red[t + s];
        __syncthreads();
    }
    if (t == 0) out[g] = red[0] + bl2[0];
}

// ---------------- launcher --------------------------------------------------
extern "C" void kernel_launch(void* const* d_in, const int* in_sizes, int n_in,
                              void* d_out, int out_size) {
    const float* x        = (const float*)d_in[0];
    const void*  ei       = d_in[1];
    const float* x_scalar = (const float*)d_in[2];
    const void*  bi       = d_in[3];
    const float* W0  = (const float*)d_in[4];
    const float* b0  = (const float*)d_in[5];
    const float* W1  = (const float*)d_in[6];
    const float* b1  = (const float*)d_in[7];
    const float* W2  = (const float*)d_in[8];
    const float* b2  = (const float*)d_in[9];
    const float* W3  = (const float*)d_in[10];
    const float* b3  = (const float*)d_in[11];
    const float* Wl1 = (const float*)d_in[12];
    const float* bl1 = (const float*)d_in[13];
    const float* Wl2 = (const float*)d_in[14];
    const float* bl2 = (const float*)d_in[15];
    float* out = (float*)d_out;

    float *bufA, *bufB, *hw;
    cudaGetSymbolAddress((void**)&bufA, g_bufA);
    cudaGetSymbolAddress((void**)&bufB, g_bufB);
    cudaGetSymbolAddress((void**)&hw,   g_hw);

    const int TB = 256;
    int gridN  = (N_NODES + TB - 1) / TB;              // 196
    int gridE  = (N_EDGES + TB - 1) / TB;              // 1563
    int gridNE = (N_NODES * EMB + TB - 1) / TB;        // 39063
    int gridAg = (N_NODES * 32 + TB - 1) / TB;         // 6250 (warp per node)
    int gridGm = (N_NODES + BM - 1) / BM;              // 782

    // preprocessing (graph structure, once per launch)
    detect_kernel<<<1, 32>>>(ei, bi);
    init_kernel<<<gridN, TB>>>();
    count_deg_kernel<<<gridE, TB>>>(ei);
    scan_part_kernel<<<SCAN_NB, SCAN_B>>>();
    scan_top_kernel<<<1, 64>>>();
    scan_final_kernel<<<SCAN_NB, SCAN_B>>>();          // also writes g_dinv
    scatter_kernel<<<gridE, TB>>>(ei);
    count_batch_kernel<<<gridN, TB>>>(bi);
    scan_goff_kernel<<<1, 512>>>();

    // layer 0
    gemm0_kernel<<<gridNE, TB>>>(x, W0, hw);
    aggregate_kernel<<<gridAg, TB>>>(hw, b0, bufA);
    // layer 1
    gemm_tf32_kernel<<<gridGm, 256>>>(bufA, W1, hw);
    aggregate_kernel<<<gridAg, TB>>>(hw, b1, bufB);
    // layer 2
    gemm_tf32_kernel<<<gridGm, 256>>>(bufB, W2, hw);
    aggregate_kernel<<<gridAg, TB>>>(hw, b2, bufA);
    // layer 3
    gemm_tf32_kernel<<<gridGm, 256>>>(bufA, W3, hw);
    aggregate_kernel<<<gridAg, TB>>>(hw, b3, bufB);

    // pool + MLP head
    pool_kernel<<<N_GRAPHS, 256>>>(bufB);
    mlp_kernel<<<N_GRAPHS, HID>>>(x_scalar, Wl1, bl1, Wl2, bl2, out);
}

// round 8
// speedup vs baseline: 1.9820x; 1.5105x over previous
#include <cuda_runtime.h>
#include <cuda_bf16.h>
#include <cstdint>

#define N_NODES  50000
#define N_EDGES  400000
#define N_GRAPHS 500
#define N_FEAT   4
#define EMB      200
#define HID      128

// padded GEMM dims
#define KPAD 208            // K padded (13 chunks of 16)
#define NPAD 208            // N padded
#define NKP  (KPAD / 2)     // 104 k-pairs

// ---------------- device scratch (no runtime allocation allowed) ----------
__device__ float g_bufA[(size_t)N_NODES * EMB];
__device__ float g_bufB[(size_t)N_NODES * EMB];
__device__ float g_hw  [(size_t)N_NODES * EMB];
__device__ float g_dinv[N_NODES];
__device__ int   g_deg [N_NODES];
__device__ int   g_off [N_NODES + 1];
__device__ int   g_cur [N_NODES];
__device__ int   g_csr_src [N_EDGES];
__device__ float g_csr_coef[N_EDGES];
__device__ int   g_flag_ei;
__device__ int   g_flag_bi;
__device__ float g_pool[N_GRAPHS * EMB];
__device__ int   g_gcnt[N_GRAPHS];
__device__ int   g_goff[N_GRAPHS];
__device__ int   g_part [64];
__device__ int   g_pscan[64];
// packed bf16 hi/lo splits of W1..W3: [layer][kpair][n] as (bf16 k, bf16 k+1)
__device__ uint32_t g_Whi[3][NKP * NPAD];
__device__ uint32_t g_Wlo[3][NKP * NPAD];

// ---------------- dtype detection ----------------------------------------
__global__ void detect_kernel(const void* ei, const void* bi) {
    if (threadIdx.x == 0 && blockIdx.x == 0) {
        const int* e32 = (const int*)ei;
        int all0 = 1;
        for (int i = 0; i < 16; i++) if (e32[2 * i + 1] != 0) all0 = 0;
        g_flag_ei = all0;
        const int* b32 = (const int*)bi;
        int all0b = 1;
        for (int i = 0; i < 16; i++) if (b32[2 * (20000 + i) + 1] != 0) all0b = 0;
        g_flag_bi = all0b;
    }
}

__device__ __forceinline__ int ld_idx(const void* p, long long i, int is64) {
    if (is64) return (int)((const long long*)p)[i];
    return ((const int*)p)[i];
}

// ---------------- graph preprocessing -------------------------------------
__global__ void init_kernel() {
    int i = blockIdx.x * blockDim.x + threadIdx.x;
    if (i < N_NODES) { g_deg[i] = 0; g_cur[i] = 0; }
    if (i < N_GRAPHS) g_gcnt[i] = 0;
}

__global__ void count_deg_kernel(const void* ei) {
    int e = blockIdx.x * blockDim.x + threadIdx.x;
    if (e >= N_EDGES) return;
    int is64 = g_flag_ei;
    int d = ld_idx(ei, (long long)N_EDGES + e, is64);
    atomicAdd(&g_deg[d], 1);
}

#define SCAN_B 1024
#define SCAN_NB ((N_NODES + SCAN_B - 1) / SCAN_B)   // 49

__global__ void scan_part_kernel() {
    __shared__ int ws[32];
    int i = blockIdx.x * SCAN_B + threadIdx.x;
    int v = (i < N_NODES) ? g_deg[i] : 0;
#pragma unroll
    for (int d = 16; d; d >>= 1) v += __shfl_down_sync(0xffffffffu, v, d);
    if ((threadIdx.x & 31) == 0) ws[threadIdx.x >> 5] = v;
    __syncthreads();
    if (threadIdx.x < 32) {
        int s = ws[threadIdx.x];
#pragma unroll
        for (int d = 16; d; d >>= 1) s += __shfl_down_sync(0xffffffffu, s, d);
        if (threadIdx.x == 0) g_part[blockIdx.x] = s;
    }
}

__global__ void scan_top_kernel() {
    __shared__ int s[64];
    int t = threadIdx.x;
    int v = (t < SCAN_NB) ? g_part[t] : 0;
    s[t] = v;
    __syncthreads();
    for (int d = 1; d < 64; d <<= 1) {
        int u = 0;
        if (t >= d) u = s[t - d];
        __syncthreads();
        s[t] += u;
        __syncthreads();
    }
    if (t < SCAN_NB) g_pscan[t] = s[t] - v;
    if (t == 0) g_off[N_NODES] = N_EDGES;
}

__global__ void scan_final_kernel() {
    __shared__ int wsum[32];
    int tid = threadIdx.x, lane = tid & 31, wid = tid >> 5;
    int i = blockIdx.x * SCAN_B + tid;
    int v = (i < N_NODES) ? g_deg[i] : 0;
    int inc = v;
#pragma unroll
    for (int d = 1; d < 32; d <<= 1) {
        int u = __shfl_up_sync(0xffffffffu, inc, d);
        if (lane >= d) inc += u;
    }
    if (lane == 31) wsum[wid] = inc;
    __syncthreads();
    if (wid == 0) {
        int s = wsum[lane];
        int si = s;
#pragma unroll
        for (int d = 1; d < 32; d <<= 1) {
            int u = __shfl_up_sync(0xffffffffu, si, d);
            if (lane >= d) si += u;
        }
        wsum[lane] = si - s;
    }
    __syncthreads();
    if (i < N_NODES) {
        g_off[i]  = g_pscan[blockIdx.x] + wsum[wid] + (inc - v);
        g_dinv[i] = rsqrtf((float)(v + 1));
    }
}

__global__ void scatter_kernel(const void* ei) {
    int e = blockIdx.x * blockDim.x + threadIdx.x;
    if (e >= N_EDGES) return;
    int is64 = g_flag_ei;
    int s = ld_idx(ei, e, is64);
    int d = ld_idx(ei, (long long)N_EDGES + e, is64);
    int p = g_off[d] + atomicAdd(&g_cur[d], 1);
    g_csr_src[p]  = s;
    g_csr_coef[p] = g_dinv[s] * g_dinv[d];
}

__global__ void count_batch_kernel(const void* bi) {
    int i = blockIdx.x * blockDim.x + threadIdx.x;
    if (i >= N_NODES) return;
    int b = ld_idx(bi, i, g_flag_bi);
    atomicAdd(&g_gcnt[b], 1);
}

__global__ void scan_goff_kernel() {
    __shared__ int s[512];
    int t = threadIdx.x;
    s[t] = (t < N_GRAPHS) ? g_gcnt[t] : 0;
    __syncthreads();
    for (int d = 1; d < 512; d <<= 1) {
        int v = 0;
        if (t >= d) v = s[t - d];
        __syncthreads();
        if (t >= d) s[t] += v;
        __syncthreads();
    }
    if (t < N_GRAPHS) g_goff[t] = (t == 0) ? 0 : s[t - 1];
}

// ---------------- W split precompute (per launch, cheap) -------------------
__device__ __forceinline__ uint32_t pack_bf2(__nv_bfloat16 lo, __nv_bfloat16 hi) {
    uint16_t a = __bfloat16_as_ushort(lo);
    uint16_t b = __bfloat16_as_ushort(hi);
    return (uint32_t)a | ((uint32_t)b << 16);
}

__global__ void split_w_kernel(const float* __restrict__ W1,
                               const float* __restrict__ W2,
                               const float* __restrict__ W3) {
    int idx = blockIdx.x * blockDim.x + threadIdx.x;
    int total = NKP * NPAD;
    if (idx >= 3 * total) return;
    int l = idx / total;
    int r = idx - l * total;
    int kp = r / NPAD, n = r - kp * NPAD;
    const float* W = (l == 0) ? W1 : (l == 1) ? W2 : W3;
    int k0 = 2 * kp, k1 = 2 * kp + 1;
    float w0 = (k0 < EMB && n < EMB) ? W[k0 * EMB + n] : 0.f;
    float w1 = (k1 < EMB && n < EMB) ? W[k1 * EMB + n] : 0.f;
    __nv_bfloat16 h0 = __float2bfloat16(w0);
    __nv_bfloat16 h1 = __float2bfloat16(w1);
    __nv_bfloat16 l0 = __float2bfloat16(w0 - __bfloat162float(h0));
    __nv_bfloat16 l1 = __float2bfloat16(w1 - __bfloat162float(h1));
    g_Whi[l][r] = pack_bf2(h0, h1);   // low 16 bits = even k
    g_Wlo[l][r] = pack_bf2(l0, l1);
}

// ---------------- GEMMs ----------------------------------------------------
// layer 0: [50000,4] @ [4,200]
__global__ void gemm0_kernel(const float* __restrict__ x,
                             const float* __restrict__ W0,
                             float* __restrict__ out) {
    int idx = blockIdx.x * blockDim.x + threadIdx.x;
    if (idx >= N_NODES * EMB) return;
    int i = idx / EMB, f = idx - i * EMB;
    const float* xr = x + i * 4;
    float s = xr[0] * __ldg(&W0[f])
            + xr[1] * __ldg(&W0[EMB + f])
            + xr[2] * __ldg(&W0[2 * EMB + f])
            + xr[3] * __ldg(&W0[3 * EMB + f]);
    out[idx] = s;
}

// layers 1-3: bf16x3 split GEMM via mma.sync.m16n8k16
// block tile 64x208, 4 warps (2M x 2N), warp tile 32x104, double-buffered.
#define GBM   64
#define ASTR  12     // A smem row stride in words (conflict-minimized)
#define BSTR  216    // B smem row stride in words (conflict-free)

#define MMA_BF16(d, a0, a1, a2, a3, b0, b1)                                   \
    asm volatile("mma.sync.aligned.m16n8k16.row.col.f32.bf16.bf16.f32 "      \
                 "{%0,%1,%2,%3}, {%4,%5,%6,%7}, {%8,%9}, {%0,%1,%2,%3};"     \
                 : "+f"((d)[0]), "+f"((d)[1]), "+f"((d)[2]), "+f"((d)[3])    \
                 : "r"(a0), "r"(a1), "r"(a2), "r"(a3), "r"(b0), "r"(b1))

__global__ __launch_bounds__(128) void gemm_bf16x3_kernel(
    const float* __restrict__ h,
    const uint32_t* __restrict__ whi, const uint32_t* __restrict__ wlo,
    float* __restrict__ out) {
    __shared__ uint32_t sAh[2][GBM * ASTR];
    __shared__ uint32_t sAl[2][GBM * ASTR];
    __shared__ uint32_t sBh[2][8 * BSTR];
    __shared__ uint32_t sBl[2][8 * BSTR];

    int tid  = threadIdx.x;
    int lane = tid & 31, warp = tid >> 5;   // 4 warps
    int wm = warp >> 1;                     // 0..1
    int wn = warp & 1;                      // 0..1
    int row0 = blockIdx.x * GBM;
    int gid = lane >> 2;                    // 0..7
    int tig = lane & 3;                     // 0..3

    float acc[13][2][4];
#pragma unroll
    for (int t = 0; t < 13; t++)
#pragma unroll
        for (int f = 0; f < 2; f++) {
            acc[t][f][0] = 0.f; acc[t][f][1] = 0.f;
            acc[t][f][2] = 0.f; acc[t][f][3] = 0.f;
        }

    float    rf[8];                 // A fp32 staging (4 k-pairs)
    uint32_t rbh[13], rbl[13];      // B staging

    auto FETCH = [&](int chunk) {
        int k0 = chunk * 16;
#pragma unroll
        for (int i = 0; i < 4; i++) {
            int idx = tid + i * 128;          // 0..511
            int r = idx >> 3, kp = idx & 7;
            int gr = row0 + r;
            int ka = k0 + 2 * kp, kb = ka + 1;
            float f0 = 0.f, f1 = 0.f;
            if (gr < N_NODES) {
                if (ka < EMB) f0 = __ldg(&h[(size_t)gr * EMB + ka]);
                if (kb < EMB) f1 = __ldg(&h[(size_t)gr * EMB + kb]);
            }
            rf[2 * i] = f0; rf[2 * i + 1] = f1;
        }
        int base = chunk * 8 * NPAD;
#pragma unroll
        for (int i = 0; i < 13; i++) {
            int idx = tid + i * 128;          // 0..1663
            int r = idx / NPAD, c = idx - r * NPAD;
            int g = base + r * NPAD + c;
            rbh[i] = __ldg(&whi[g]);
            rbl[i] = __ldg(&wlo[g]);
        }
    };
    auto STORE = [&](int buf) {
#pragma unroll
        for (int i = 0; i < 4; i++) {
            int idx = tid + i * 128;
            int r = idx >> 3, kp = idx & 7;
            float f0 = rf[2 * i], f1 = rf[2 * i + 1];
            __nv_bfloat16 h0 = __float2bfloat16(f0);
            __nv_bfloat16 h1 = __float2bfloat16(f1);
            __nv_bfloat16 l0 = __float2bfloat16(f0 - __bfloat162float(h0));
            __nv_bfloat16 l1 = __float2bfloat16(f1 - __bfloat162float(h1));
            sAh[buf][r * ASTR + kp] = pack_bf2(h0, h1);
            sAl[buf][r * ASTR + kp] = pack_bf2(l0, l1);
        }
#pragma unroll
        for (int i = 0; i < 13; i++) {
            int idx = tid + i * 128;
            int r = idx / NPAD, c = idx - r * NPAD;
            sBh[buf][r * BSTR + c] = rbh[i];
            sBl[buf][r * BSTR + c] = rbl[i];
        }
    };

    FETCH(0);
    STORE(0);
    __syncthreads();

    int ar = wm * 32 + gid;
#pragma unroll 1
    for (int ks = 0; ks < 13; ks++) {
        int cur = ks & 1;
        if (ks < 12) FETCH(ks + 1);

        // A fragments: two 16-row m-frags per warp, hi & lo splits
        uint32_t ah[8], al[8];
#pragma unroll
        for (int f = 0; f < 2; f++) {
            int r = ar + f * 16;
            ah[f * 4 + 0] = sAh[cur][r * ASTR + tig];
            ah[f * 4 + 1] = sAh[cur][(r + 8) * ASTR + tig];
            ah[f * 4 + 2] = sAh[cur][r * ASTR + tig + 4];
            ah[f * 4 + 3] = sAh[cur][(r + 8) * ASTR + tig + 4];
            al[f * 4 + 0] = sAl[cur][r * ASTR + tig];
            al[f * 4 + 1] = sAl[cur][(r + 8) * ASTR + tig];
            al[f * 4 + 2] = sAl[cur][r * ASTR + tig + 4];
            al[f * 4 + 3] = sAl[cur][(r + 8) * ASTR + tig + 4];
        }

#pragma unroll
        for (int t = 0; t < 13; t++) {
            int n = wn * 104 + t * 8 + gid;
            uint32_t bh0 = sBh[cur][tig * BSTR + n];
            uint32_t bh1 = sBh[cur][(tig + 4) * BSTR + n];
            uint32_t bl0 = sBl[cur][tig * BSTR + n];
            uint32_t bl1 = sBl[cur][(tig + 4) * BSTR + n];
            MMA_BF16(acc[t][0], ah[0], ah[1], ah[2], ah[3], bh0, bh1);
            MMA_BF16(acc[t][1], ah[4], ah[5], ah[6], ah[7], bh0, bh1);
            MMA_BF16(acc[t][0], al[0], al[1], al[2], al[3], bh0, bh1);
            MMA_BF16(acc[t][1], al[4], al[5], al[6], al[7], bh0, bh1);
            MMA_BF16(acc[t][0], ah[0], ah[1], ah[2], ah[3], bl0, bl1);
            MMA_BF16(acc[t][1], ah[4], ah[5], ah[6], ah[7], bl0, bl1);
        }

        if (ks < 12) STORE(cur ^ 1);
        __syncthreads();
    }

    // epilogue: C layout (g, 2t),(g,2t+1) / (g+8, ...)
#pragma unroll
    for (int t = 0; t < 13; t++) {
        int n = wn * 104 + t * 8 + 2 * tig;
        if (n >= EMB) continue;
#pragma unroll
        for (int f = 0; f < 2; f++) {
            int r = row0 + wm * 32 + f * 16 + gid;
            if (r < N_NODES)
                *reinterpret_cast<float2*>(&out[(size_t)r * EMB + n]) =
                    make_float2(acc[t][f][0], acc[t][f][1]);
            if (r + 8 < N_NODES)
                *reinterpret_cast<float2*>(&out[(size_t)(r + 8) * EMB + n]) =
                    make_float2(acc[t][f][2], acc[t][f][3]);
        }
    }
}

// ---------------- edge aggregation (gather, warp per dst node) -------------
__global__ __launch_bounds__(256) void aggregate_kernel(
    const float* __restrict__ hw, const float* __restrict__ b,
    float* __restrict__ out) {
    int warp = (blockIdx.x * blockDim.x + threadIdx.x) >> 5;
    int lane = threadIdx.x & 31;
    if (warp >= N_NODES) return;
    int i = warp;

    float dv = g_dinv[i];
    float selfc = dv * dv;

    const float4* hi4 = reinterpret_cast<const float4*>(hw + (size_t)i * EMB);
    float4 a0 = make_float4(0.f, 0.f, 0.f, 0.f);
    float4 a1 = a0;
    {
        float4 v0 = hi4[lane];
        a0.x = selfc * v0.x; a0.y = selfc * v0.y; a0.z = selfc * v0.z; a0.w = selfc * v0.w;
        if (lane < 18) {
            float4 v1 = hi4[32 + lane];
            a1.x = selfc * v1.x; a1.y = selfc * v1.y; a1.z = selfc * v1.z; a1.w = selfc * v1.w;
        }
    }

    int e0 = g_off[i], e1 = g_off[i + 1];
    for (int e = e0; e < e1; e++) {
        int   s = g_csr_src[e];
        float c = g_csr_coef[e];
        const float4* hs4 = reinterpret_cast<const float4*>(hw + (size_t)s * EMB);
        float4 v0 = hs4[lane];
        a0.x += c * v0.x; a0.y += c * v0.y; a0.z += c * v0.z; a0.w += c * v0.w;
        if (lane < 18) {
            float4 v1 = hs4[32 + lane];
            a1.x += c * v1.x; a1.y += c * v1.y; a1.z += c * v1.z; a1.w += c * v1.w;
        }
    }

    const float4* b4 = reinterpret_cast<const float4*>(b);
    float4* o4 = reinterpret_cast<float4*>(out + (size_t)i * EMB);
    {
        float4 bb = b4[lane];
        float4 v;
        v.x = a0.x + bb.x; v.y = a0.y + bb.y; v.z = a0.z + bb.z; v.w = a0.w + bb.w;
        v.x = v.x > 0.f ? v.x : 0.01f * v.x;
        v.y = v.y > 0.f ? v.y : 0.01f * v.y;
        v.z = v.z > 0.f ? v.z : 0.01f * v.z;
        v.w = v.w > 0.f ? v.w : 0.01f * v.w;
        o4[lane] = v;
        if (lane < 18) {
            float4 bb1 = b4[32 + lane];
            float4 w;
            w.x = a1.x + bb1.x; w.y = a1.y + bb1.y; w.z = a1.z + bb1.z; w.w = a1.w + bb1.w;
            w.x = w.x > 0.f ? w.x : 0.01f * w.x;
            w.y = w.y > 0.f ? w.y : 0.01f * w.y;
            w.z = w.z > 0.f ? w.z : 0.01f * w.z;
            w.w = w.w > 0.f ? w.w : 0.01f * w.w;
            o4[32 + lane] = w;
        }
    }
}

// ---------------- pooling + MLP head ---------------------------------------
__global__ void pool_kernel(const float* __restrict__ h) {
    int g = blockIdx.x;
    int t = threadIdx.x;
    if (t >= EMB) return;
    int r0 = g_goff[g];
    int n = g_gcnt[g];
    float s = 0.f;
    for (int j = 0; j < n; j++) s += h[(size_t)(r0 + j) * EMB + t];
    g_pool[g * EMB + t] = s / fmaxf((float)n, 1.0f);
}

__global__ __launch_bounds__(HID) void mlp_kernel(
    const float* __restrict__ xs,
    const float* __restrict__ Wl1, const float* __restrict__ bl1,
    const float* __restrict__ Wl2, const float* __restrict__ bl2,
    float* __restrict__ out) {
    int g = blockIdx.x;
    int t = threadIdx.x;
    __shared__ float gv[EMB + N_FEAT];
    __shared__ float red[HID];

    for (int k = t; k < EMB; k += HID) gv[k] = g_pool[g * EMB + k];
    if (t < N_FEAT) gv[EMB + t] = xs[g * N_FEAT + t];
    __syncthreads();

    float acc = bl1[t];
    for (int k = 0; k < EMB + N_FEAT; k++) acc += gv[k] * Wl1[k * HID + t];
    acc = acc > 0.f ? acc : 0.01f * acc;
    red[t] = acc * Wl2[t];
    __syncthreads();
    for (int s = HID / 2; s > 0; s >>= 1) {
        if (t < s) red[t] += red[t + s];
        __syncthreads();
    }
    if (t == 0) out[g] = red[0] + bl2[0];
}

// ---------------- launcher --------------------------------------------------
extern "C" void kernel_launch(void* const* d_in, const int* in_sizes, int n_in,
                              void* d_out, int out_size) {
    const float* x        = (const float*)d_in[0];
    const void*  ei       = d_in[1];
    const float* x_scalar = (const float*)d_in[2];
    const void*  bi       = d_in[3];
    const float* W0  = (const float*)d_in[4];
    const float* b0  = (const float*)d_in[5];
    const float* W1  = (const float*)d_in[6];
    const float* b1  = (const float*)d_in[7];
    const float* W2  = (const float*)d_in[8];
    const float* b2  = (const float*)d_in[9];
    const float* W3  = (const float*)d_in[10];
    const float* b3  = (const float*)d_in[11];
    const float* Wl1 = (const float*)d_in[12];
    const float* bl1 = (const float*)d_in[13];
    const float* Wl2 = (const float*)d_in[14];
    const float* bl2 = (const float*)d_in[15];
    float* out = (float*)d_out;

    float *bufA, *bufB, *hw;
    uint32_t *whi, *wlo;
    cudaGetSymbolAddress((void**)&bufA, g_bufA);
    cudaGetSymbolAddress((void**)&bufB, g_bufB);
    cudaGetSymbolAddress((void**)&hw,   g_hw);
    cudaGetSymbolAddress((void**)&whi,  g_Whi);
    cudaGetSymbolAddress((void**)&wlo,  g_Wlo);

    const int TB = 256;
    int gridN  = (N_NODES + TB - 1) / TB;
    int gridE  = (N_EDGES + TB - 1) / TB;
    int gridNE = (N_NODES * EMB + TB - 1) / TB;
    int gridAg = (N_NODES * 32 + TB - 1) / TB;
    int gridGm = (N_NODES + GBM - 1) / GBM;            // 782
    int gridW  = (3 * NKP * NPAD + TB - 1) / TB;

    // preprocessing
    detect_kernel<<<1, 32>>>(ei, bi);
    init_kernel<<<gridN, TB>>>();
    split_w_kernel<<<gridW, TB>>>(W1, W2, W3);
    count_deg_kernel<<<gridE, TB>>>(ei);
    scan_part_kernel<<<SCAN_NB, SCAN_B>>>();
    scan_top_kernel<<<1, 64>>>();
    scan_final_kernel<<<SCAN_NB, SCAN_B>>>();
    scatter_kernel<<<gridE, TB>>>(ei);
    count_batch_kernel<<<gridN, TB>>>(bi);
    scan_goff_kernel<<<1, 512>>>();

    const int WTOT = NKP * NPAD;

    // layer 0
    gemm0_kernel<<<gridNE, TB>>>(x, W0, hw);
    aggregate_kernel<<<gridAg, TB>>>(hw, b0, bufA);
    // layer 1
    gemm_bf16x3_kernel<<<gridGm, 128>>>(bufA, whi, wlo, hw);
    aggregate_kernel<<<gridAg, TB>>>(hw, b1, bufB);
    // layer 2
    gemm_bf16x3_kernel<<<gridGm, 128>>>(bufB, whi + WTOT, wlo + WTOT, hw);
    aggregate_kernel<<<gridAg, TB>>>(hw, b2, bufA);
    // layer 3
    gemm_bf16x3_kernel<<<gridGm, 128>>>(bufA, whi + 2 * WTOT, wlo + 2 * WTOT, hw);
    aggregate_kernel<<<gridAg, TB>>>(hw, b3, bufB);

    // pool + MLP head
    pool_kernel<<<N_GRAPHS, 256>>>(bufB);
    mlp_kernel<<<N_GRAPHS, HID>>>(x_scalar, Wl1, bl1, Wl2, bl2, out);
}

// round 10
// speedup vs baseline: 2.1386x; 1.0790x over previous
#include <cuda_runtime.h>
#include <cuda_bf16.h>
#include <cstdint>

#define N_NODES  50000
#define N_EDGES  400000
#define N_GRAPHS 500
#define N_FEAT   4
#define EMB      200
#define HID      128

// padded GEMM dims
#define KPAD 208            // K padded (13 chunks of 16)
#define NPAD 208            // N padded
#define NKP  (KPAD / 2)     // 104 k-pairs

// ---------------- device scratch (no runtime allocation allowed) ----------
__device__ float g_bufA[(size_t)N_NODES * EMB];
__device__ float g_bufB[(size_t)N_NODES * EMB];
__device__ float g_hw  [(size_t)N_NODES * EMB];
__device__ float g_dinv[N_NODES];
__device__ int   g_deg [N_NODES];
__device__ int   g_off [N_NODES + 1];
__device__ int   g_cur [N_NODES];
__device__ int   g_csr_src [N_EDGES];
__device__ float g_csr_coef[N_EDGES];
__device__ int   g_flag_ei;
__device__ int   g_flag_bi;
__device__ float g_pool[N_GRAPHS * EMB];
__device__ int   g_gcnt[N_GRAPHS];
__device__ int   g_goff[N_GRAPHS];
__device__ int   g_part [64];
__device__ int   g_pscan[64];
// packed bf16 hi/lo splits of W1..W3: [layer][kpair][n] as (bf16 k, bf16 k+1)
__device__ uint32_t g_Whi[3][NKP * NPAD];
__device__ uint32_t g_Wlo[3][NKP * NPAD];

// ---------------- dtype detection ----------------------------------------
__global__ void detect_kernel(const void* ei, const void* bi) {
    if (threadIdx.x == 0 && blockIdx.x == 0) {
        const int* e32 = (const int*)ei;
        int all0 = 1;
        for (int i = 0; i < 16; i++) if (e32[2 * i + 1] != 0) all0 = 0;
        g_flag_ei = all0;
        const int* b32 = (const int*)bi;
        int all0b = 1;
        for (int i = 0; i < 16; i++) if (b32[2 * (20000 + i) + 1] != 0) all0b = 0;
        g_flag_bi = all0b;
    }
}

__device__ __forceinline__ int ld_idx(const void* p, long long i, int is64) {
    if (is64) return (int)((const long long*)p)[i];
    return ((const int*)p)[i];
}

// ---------------- graph preprocessing -------------------------------------
__global__ void init_kernel() {
    int i = blockIdx.x * blockDim.x + threadIdx.x;
    if (i < N_NODES) { g_deg[i] = 0; g_cur[i] = 0; }
    if (i < N_GRAPHS) g_gcnt[i] = 0;
}

// fused: degree histogram (edges) + per-graph node count (nodes)
__global__ void count_kernel(const void* ei, const void* bi) {
    int e = blockIdx.x * blockDim.x + threadIdx.x;
    if (e < N_EDGES) {
        int d = ld_idx(ei, (long long)N_EDGES + e, g_flag_ei);
        atomicAdd(&g_deg[d], 1);
    }
    if (e < N_NODES) {
        int b = ld_idx(bi, e, g_flag_bi);
        atomicAdd(&g_gcnt[b], 1);
    }
}

#define SCAN_B 1024
#define SCAN_NB ((N_NODES + SCAN_B - 1) / SCAN_B)   // 49

__global__ void scan_part_kernel() {
    __shared__ int ws[32];
    int i = blockIdx.x * SCAN_B + threadIdx.x;
    int v = (i < N_NODES) ? g_deg[i] : 0;
#pragma unroll
    for (int d = 16; d; d >>= 1) v += __shfl_down_sync(0xffffffffu, v, d);
    if ((threadIdx.x & 31) == 0) ws[threadIdx.x >> 5] = v;
    __syncthreads();
    if (threadIdx.x < 32) {
        int s = ws[threadIdx.x];
#pragma unroll
        for (int d = 16; d; d >>= 1) s += __shfl_down_sync(0xffffffffu, s, d);
        if (threadIdx.x == 0) g_part[blockIdx.x] = s;
    }
}

// fused: top-level scan of block partials + per-graph offset scan
__global__ void scan_top_kernel() {
    __shared__ int s[64];
    __shared__ int sg[512];
    int t = threadIdx.x;
    if (t < 64) {
        int v = (t < SCAN_NB) ? g_part[t] : 0;
        s[t] = v;
    }
    sg[t] = (t < N_GRAPHS) ? g_gcnt[t] : 0;
    __syncthreads();
    // top scan (64 lanes, serial in-warp-style ladder)
    if (t < 64) {
        // done by all 64 threads with syncs below via full-block barriers
    }
    for (int d = 1; d < 64; d <<= 1) {
        int u = 0;
        if (t < 64 && t >= d) u = s[t - d];
        __syncthreads();
        if (t < 64 && t >= d) s[t] += u;
        __syncthreads();
    }
    for (int d = 1; d < 512; d <<= 1) {
        int u = 0;
        if (t >= d) u = sg[t - d];
        __syncthreads();
        if (t >= d) sg[t] += u;
        __syncthreads();
    }
    if (t < SCAN_NB) g_pscan[t] = s[t] - g_part[t];
    if (t == 0) g_off[N_NODES] = N_EDGES;
    if (t < N_GRAPHS) g_goff[t] = (t == 0) ? 0 : sg[t - 1];
}

__global__ void scan_final_kernel() {
    __shared__ int wsum[32];
    int tid = threadIdx.x, lane = tid & 31, wid = tid >> 5;
    int i = blockIdx.x * SCAN_B + tid;
    int v = (i < N_NODES) ? g_deg[i] : 0;
    int inc = v;
#pragma unroll
    for (int d = 1; d < 32; d <<= 1) {
        int u = __shfl_up_sync(0xffffffffu, inc, d);
        if (lane >= d) inc += u;
    }
    if (lane == 31) wsum[wid] = inc;
    __syncthreads();
    if (wid == 0) {
        int s = wsum[lane];
        int si = s;
#pragma unroll
        for (int d = 1; d < 32; d <<= 1) {
            int u = __shfl_up_sync(0xffffffffu, si, d);
            if (lane >= d) si += u;
        }
        wsum[lane] = si - s;
    }
    __syncthreads();
    if (i < N_NODES) {
        g_off[i]  = g_pscan[blockIdx.x] + wsum[wid] + (inc - v);
        g_dinv[i] = rsqrtf((float)(v + 1));
    }
}

__global__ void scatter_kernel(const void* ei) {
    int e = blockIdx.x * blockDim.x + threadIdx.x;
    if (e >= N_EDGES) return;
    int is64 = g_flag_ei;
    int s = ld_idx(ei, e, is64);
    int d = ld_idx(ei, (long long)N_EDGES + e, is64);
    int p = g_off[d] + atomicAdd(&g_cur[d], 1);
    g_csr_src[p]  = s;
    g_csr_coef[p] = g_dinv[s] * g_dinv[d];
}

// ---------------- W split precompute (per launch, cheap) -------------------
__device__ __forceinline__ uint32_t pack_bf2(__nv_bfloat16 lo, __nv_bfloat16 hi) {
    uint16_t a = __bfloat16_as_ushort(lo);
    uint16_t b = __bfloat16_as_ushort(hi);
    return (uint32_t)a | ((uint32_t)b << 16);
}

__global__ void split_w_kernel(const float* __restrict__ W1,
                               const float* __restrict__ W2,
                               const float* __restrict__ W3) {
    int idx = blockIdx.x * blockDim.x + threadIdx.x;
    int total = NKP * NPAD;
    if (idx >= 3 * total) return;
    int l = idx / total;
    int r = idx - l * total;
    int kp = r / NPAD, n = r - kp * NPAD;
    const float* W = (l == 0) ? W1 : (l == 1) ? W2 : W3;
    int k0 = 2 * kp, k1 = 2 * kp + 1;
    float w0 = (k0 < EMB && n < EMB) ? W[k0 * EMB + n] : 0.f;
    float w1 = (k1 < EMB && n < EMB) ? W[k1 * EMB + n] : 0.f;
    __nv_bfloat16 h0 = __float2bfloat16(w0);
    __nv_bfloat16 h1 = __float2bfloat16(w1);
    __nv_bfloat16 l0 = __float2bfloat16(w0 - __bfloat162float(h0));
    __nv_bfloat16 l1 = __float2bfloat16(w1 - __bfloat162float(h1));
    g_Whi[l][r] = pack_bf2(h0, h1);   // low 16 bits = even k
    g_Wlo[l][r] = pack_bf2(l0, l1);
}

// ---------------- layer 0: aggregate(x) then (Ax)@W0 (linearity) -----------
__global__ void aggregate4_kernel(const float* __restrict__ x,
                                  float* __restrict__ outx) {
    int i = blockIdx.x * blockDim.x + threadIdx.x;
    if (i >= N_NODES) return;
    float dv = g_dinv[i];
    float selfc = dv * dv;
    float4 xi = *reinterpret_cast<const float4*>(x + (size_t)i * 4);
    float4 a = make_float4(selfc * xi.x, selfc * xi.y, selfc * xi.z, selfc * xi.w);
    int e0 = g_off[i], e1 = g_off[i + 1];
    for (int e = e0; e < e1; e++) {
        int s = g_csr_src[e];
        float c = g_csr_coef[e];
        float4 v = *reinterpret_cast<const float4*>(x + (size_t)s * 4);
        a.x += c * v.x; a.y += c * v.y; a.z += c * v.z; a.w += c * v.w;
    }
    *reinterpret_cast<float4*>(outx + (size_t)i * 4) = a;
}

__global__ void gemm0f_kernel(const float* __restrict__ xa,
                              const float* __restrict__ W0,
                              const float* __restrict__ b0,
                              float* __restrict__ out) {
    int idx = blockIdx.x * blockDim.x + threadIdx.x;
    if (idx >= N_NODES * EMB) return;
    int i = idx / EMB, f = idx - i * EMB;
    const float* xr = xa + (size_t)i * 4;
    float s = xr[0] * __ldg(&W0[f])
            + xr[1] * __ldg(&W0[EMB + f])
            + xr[2] * __ldg(&W0[2 * EMB + f])
            + xr[3] * __ldg(&W0[3 * EMB + f])
            + __ldg(&b0[f]);
    out[idx] = s > 0.f ? s : 0.01f * s;
}

// ---------------- layers 1-3: bf16x3 split GEMM via mma.sync.m16n8k16 ------
// block tile 64x208, 4 warps (2M x 2N), warp tile 32x104, double-buffered.
#define GBM   64
#define ASTR  12     // A smem row stride in words
#define BSTR  216    // B smem row stride in words

#define MMA_BF16(d, a0, a1, a2, a3, b0, b1)                                   \
    asm volatile("mma.sync.aligned.m16n8k16.row.col.f32.bf16.bf16.f32 "      \
                 "{%0,%1,%2,%3}, {%4,%5,%6,%7}, {%8,%9}, {%0,%1,%2,%3};"     \
                 : "+f"((d)[0]), "+f"((d)[1]), "+f"((d)[2]), "+f"((d)[3])    \
                 : "r"(a0), "r"(a1), "r"(a2), "r"(a3), "r"(b0), "r"(b1))

__global__ __launch_bounds__(128) void gemm_bf16x3_kernel(
    const float* __restrict__ h,
    const uint32_t* __restrict__ whi, const uint32_t* __restrict__ wlo,
    float* __restrict__ out) {
    __shared__ uint32_t sAh[2][GBM * ASTR];
    __shared__ uint32_t sAl[2][GBM * ASTR];
    __shared__ uint32_t sBh[2][8 * BSTR];
    __shared__ uint32_t sBl[2][8 * BSTR];

    int tid  = threadIdx.x;
    int lane = tid & 31, warp = tid >> 5;   // 4 warps
    int wm = warp >> 1;                     // 0..1
    int wn = warp & 1;                      // 0..1
    int row0 = blockIdx.x * GBM;
    int gid = lane >> 2;                    // 0..7
    int tig = lane & 3;                     // 0..3

    float acc[13][2][4];
#pragma unroll
    for (int t = 0; t < 13; t++)
#pragma unroll
        for (int f = 0; f < 2; f++) {
            acc[t][f][0] = 0.f; acc[t][f][1] = 0.f;
            acc[t][f][2] = 0.f; acc[t][f][3] = 0.f;
        }

    float    rf[8];
    uint32_t rbh[13], rbl[13];

    auto FETCH = [&](int chunk) {
        int k0 = chunk * 16;
#pragma unroll
        for (int i = 0; i < 4; i++) {
            int idx = tid + i * 128;
            int r = idx >> 3, kp = idx & 7;
            int gr = row0 + r;
            int ka = k0 + 2 * kp, kb = ka + 1;
            float f0 = 0.f, f1 = 0.f;
            if (gr < N_NODES) {
                if (ka < EMB) f0 = __ldg(&h[(size_t)gr * EMB + ka]);
                if (kb < EMB) f1 = __ldg(&h[(size_t)gr * EMB + kb]);
            }
            rf[2 * i] = f0; rf[2 * i + 1] = f1;
        }
        int base = chunk * 8 * NPAD;
#pragma unroll
        for (int i = 0; i < 13; i++) {
            int idx = tid + i * 128;
            int r = idx / NPAD, c = idx - r * NPAD;
            int g = base + r * NPAD + c;
            rbh[i] = __ldg(&whi[g]);
            rbl[i] = __ldg(&wlo[g]);
        }
    };
    auto STORE = [&](int buf) {
#pragma unroll
        for (int i = 0; i < 4; i++) {
            int idx = tid + i * 128;
            int r = idx >> 3, kp = idx & 7;
            float f0 = rf[2 * i], f1 = rf[2 * i + 1];
            __nv_bfloat16 h0 = __float2bfloat16(f0);
            __nv_bfloat16 h1 = __float2bfloat16(f1);
            __nv_bfloat16 l0 = __float2bfloat16(f0 - __bfloat162float(h0));
            __nv_bfloat16 l1 = __float2bfloat16(f1 - __bfloat162float(h1));
            sAh[buf][r * ASTR + kp] = pack_bf2(h0, h1);
            sAl[buf][r * ASTR + kp] = pack_bf2(l0, l1);
        }
#pragma unroll
        for (int i = 0; i < 13; i++) {
            int idx = tid + i * 128;
            int r = idx / NPAD, c = idx - r * NPAD;
            sBh[buf][r * BSTR + c] = rbh[i];
            sBl[buf][r * BSTR + c] = rbl[i];
        }
    };

    FETCH(0);
    STORE(0);
    __syncthreads();

    int ar = wm * 32 + gid;
#pragma unroll 1
    for (int ks = 0; ks < 13; ks++) {
        int cur = ks & 1;
        if (ks < 12) FETCH(ks + 1);

        uint32_t ah[8], al[8];
#pragma unroll
        for (int f = 0; f < 2; f++) {
            int r = ar + f * 16;
            ah[f * 4 + 0] = sAh[cur][r * ASTR + tig];
            ah[f * 4 + 1] = sAh[cur][(r + 8) * ASTR + tig];
            ah[f * 4 + 2] = sAh[cur][r * ASTR + tig + 4];
            ah[f * 4 + 3] = sAh[cur][(r + 8) * ASTR + tig + 4];
            al[f * 4 + 0] = sAl[cur][r * ASTR + tig];
            al[f * 4 + 1] = sAl[cur][(r + 8) * ASTR + tig];
            al[f * 4 + 2] = sAl[cur][r * ASTR + tig + 4];
            al[f * 4 + 3] = sAl[cur][(r + 8) * ASTR + tig + 4];
        }

#pragma unroll
        for (int t = 0; t < 13; t++) {
            int n = wn * 104 + t * 8 + gid;
            uint32_t bh0 = sBh[cur][tig * BSTR + n];
            uint32_t bh1 = sBh[cur][(tig + 4) * BSTR + n];
            uint32_t bl0 = sBl[cur][tig * BSTR + n];
            uint32_t bl1 = sBl[cur][(tig + 4) * BSTR + n];
            MMA_BF16(acc[t][0], ah[0], ah[1], ah[2], ah[3], bh0, bh1);
            MMA_BF16(acc[t][1], ah[4], ah[5], ah[6], ah[7], bh0, bh1);
            MMA_BF16(acc[t][0], al[0], al[1], al[2], al[3], bh0, bh1);
            MMA_BF16(acc[t][1], al[4], al[5], al[6], al[7], bh0, bh1);
            MMA_BF16(acc[t][0], ah[0], ah[1], ah[2], ah[3], bl0, bl1);
            MMA_BF16(acc[t][1], ah[4], ah[5], ah[6], ah[7], bl0, bl1);
        }

        if (ks < 12) STORE(cur ^ 1);
        __syncthreads();
    }

#pragma unroll
    for (int t = 0; t < 13; t++) {
        int n = wn * 104 + t * 8 + 2 * tig;
        if (n >= EMB) continue;
#pragma unroll
        for (int f = 0; f < 2; f++) {
            int r = row0 + wm * 32 + f * 16 + gid;
            if (r < N_NODES)
                *reinterpret_cast<float2*>(&out[(size_t)r * EMB + n]) =
                    make_float2(acc[t][f][0], acc[t][f][1]);
            if (r + 8 < N_NODES)
                *reinterpret_cast<float2*>(&out[(size_t)(r + 8) * EMB + n]) =
                    make_float2(acc[t][f][2], acc[t][f][3]);
        }
    }
}

// ---------------- edge aggregation (gather, warp per dst node) -------------
__global__ __launch_bounds__(256) void aggregate_kernel(
    const float* __restrict__ hw, const float* __restrict__ b,
    float* __restrict__ out) {
    int warp = (blockIdx.x * blockDim.x + threadIdx.x) >> 5;
    int lane = threadIdx.x & 31;
    if (warp >= N_NODES) return;
    int i = warp;

    float dv = g_dinv[i];
    float selfc = dv * dv;

    const float4* hi4 = reinterpret_cast<const float4*>(hw + (size_t)i * EMB);
    float4 a0 = make_float4(0.f, 0.f, 0.f, 0.f);
    float4 a1 = a0;
    {
        float4 v0 = hi4[lane];
        a0.x = selfc * v0.x; a0.y = selfc * v0.y; a0.z = selfc * v0.z; a0.w = selfc * v0.w;
        if (lane < 18) {
            float4 v1 = hi4[32 + lane];
            a1.x = selfc * v1.x; a1.y = selfc * v1.y; a1.z = selfc * v1.z; a1.w = selfc * v1.w;
        }
    }

    int e0 = g_off[i], e1 = g_off[i + 1];
    for (int e = e0; e < e1; e++) {
        int   s = g_csr_src[e];
        float c = g_csr_coef[e];
        const float4* hs4 = reinterpret_cast<const float4*>(hw + (size_t)s * EMB);
        float4 v0 = hs4[lane];
        a0.x += c * v0.x; a0.y += c * v0.y; a0.z += c * v0.z; a0.w += c * v0.w;
        if (lane < 18) {
            float4 v1 = hs4[32 + lane];
            a1.x += c * v1.x; a1.y += c * v1.y; a1.z += c * v1.z; a1.w += c * v1.w;
        }
    }

    const float4* b4 = reinterpret_cast<const float4*>(b);
    float4* o4 = reinterpret_cast<float4*>(out + (size_t)i * EMB);
    {
        float4 bb = b4[lane];
        float4 v;
        v.x = a0.x + bb.x; v.y = a0.y + bb.y; v.z = a0.z + bb.z; v.w = a0.w + bb.w;
        v.x = v.x > 0.f ? v.x : 0.01f * v.x;
        v.y = v.y > 0.f ? v.y : 0.01f * v.y;
        v.z = v.z > 0.f ? v.z : 0.01f * v.z;
        v.w = v.w > 0.f ? v.w : 0.01f * v.w;
        o4[lane] = v;
        if (lane < 18) {
            float4 bb1 = b4[32 + lane];
            float4 w;
            w.x = a1.x + bb1.x; w.y = a1.y + bb1.y; w.z = a1.z + bb1.z; w.w = a1.w + bb1.w;
            w.x = w.x > 0.f ? w.x : 0.01f * w.x;
            w.y = w.y > 0.f ? w.y : 0.01f * w.y;
            w.z = w.z > 0.f ? w.z : 0.01f * w.z;
            w.w = w.w > 0.f ? w.w : 0.01f * w.w;
            o4[32 + lane] = w;
        }
    }
}

// ---------------- pooling + MLP head ---------------------------------------
__global__ void pool_kernel(const float* __restrict__ h) {
    int g = blockIdx.x;
    int t = threadIdx.x;
    if (t >= EMB) return;
    int r0 = g_goff[g];
    int n = g_gcnt[g];
    float s = 0.f;
    for (int j = 0; j < n; j++) s += h[(size_t)(r0 + j) * EMB + t];
    g_pool[g * EMB + t] = s / fmaxf((float)n, 1.0f);
}

__global__ __launch_bounds__(HID) void mlp_kernel(
    const float* __restrict__ xs,
    const float* __restrict__ Wl1, const float* __restrict__ bl1,
    const float* __restrict__ Wl2, const float* __restrict__ bl2,
    float* __restrict__ out) {
    int g = blockIdx.x;
    int t = threadIdx.x;
    __shared__ float gv[EMB + N_FEAT];
    __shared__ float red[HID];

    for (int k = t; k < EMB; k += HID) gv[k] = g_pool[g * EMB + k];
    if (t < N_FEAT) gv[EMB + t] = xs[g * N_FEAT + t];
    __syncthreads();

    float acc = bl1[t];
    for (int k = 0; k < EMB + N_FEAT; k++) acc += gv[k] * Wl1[k * HID + t];
    acc = acc > 0.f ? acc : 0.01f * acc;
    red[t] = acc * Wl2[t];
    __syncthreads();
    for (int s = HID / 2; s > 0; s >>= 1) {
        if (t < s) red[t] += red[t + s];
        __syncthreads();
    }
    if (t == 0) out[g] = red[0] + bl2[0];
}

// ---------------- launcher --------------------------------------------------
extern "C" void kernel_launch(void* const* d_in, const int* in_sizes, int n_in,
                              void* d_out, int out_size) {
    const float* x        = (const float*)d_in[0];
    const void*  ei       = d_in[1];
    const float* x_scalar = (const float*)d_in[2];
    const void*  bi       = d_in[3];
    const float* W0  = (const float*)d_in[4];
    const float* b0  = (const float*)d_in[5];
    const float* W1  = (const float*)d_in[6];
    const float* b1  = (const float*)d_in[7];
    const float* W2  = (const float*)d_in[8];
    const float* b2  = (const float*)d_in[9];
    const float* W3  = (const float*)d_in[10];
    const float* b3  = (const float*)d_in[11];
    const float* Wl1 = (const float*)d_in[12];
    const float* bl1 = (const float*)d_in[13];
    const float* Wl2 = (const float*)d_in[14];
    const float* bl2 = (const float*)d_in[15];
    float* out = (float*)d_out;

    float *bufA, *bufB, *hw;
    uint32_t *whi, *wlo;
    cudaGetSymbolAddress((void**)&bufA, g_bufA);
    cudaGetSymbolAddress((void**)&bufB, g_bufB);
    cudaGetSymbolAddress((void**)&hw,   g_hw);
    cudaGetSymbolAddress((void**)&whi,  g_Whi);
    cudaGetSymbolAddress((void**)&wlo,  g_Wlo);

    const int TB = 256;
    int gridN  = (N_NODES + TB - 1) / TB;
    int gridE  = (N_EDGES + TB - 1) / TB;
    int gridNE = (N_NODES * EMB + TB - 1) / TB;
    int gridAg = (N_NODES * 32 + TB - 1) / TB;
    int gridGm = (N_NODES + GBM - 1) / GBM;            // 782
    int gridW  = (3 * NKP * NPAD + TB - 1) / TB;

    // preprocessing (8 launches)
    detect_kernel<<<1, 32>>>(ei, bi);
    init_kernel<<<gridN, TB>>>();
    split_w_kernel<<<gridW, TB>>>(W1, W2, W3);
    count_kernel<<<gridE, TB>>>(ei, bi);
    scan_part_kernel<<<SCAN_NB, SCAN_B>>>();
    scan_top_kernel<<<1, 512>>>();
    scan_final_kernel<<<SCAN_NB, SCAN_B>>>();
    scatter_kernel<<<gridE, TB>>>(ei);

    const int WTOT = NKP * NPAD;

    // layer 0 (aggregate-first by linearity; bias+leaky fused into gemm0f)
    aggregate4_kernel<<<gridN, TB>>>(x, hw);
    gemm0f_kernel<<<gridNE, TB>>>(hw, W0, b0, bufA);

    // layer 1
    gemm_bf16x3_kernel<<<gridGm, 128>>>(bufA, whi, wlo, hw);
    aggregate_kernel<<<gridAg, TB>>>(hw, b1, bufB);
    // layer 2
    gemm_bf16x3_kernel<<<gridGm, 128>>>(bufB, whi + WTOT, wlo + WTOT, hw);
    aggregate_kernel<<<gridAg, TB>>>(hw, b2, bufA);
    // layer 3
    gemm_bf16x3_kernel<<<gridGm, 128>>>(bufA, whi + 2 * WTOT, wlo + 2 * WTOT, hw);
    aggregate_kernel<<<gridAg, TB>>>(hw, b3, bufB);

    // pool + MLP head
    pool_kernel<<<N_GRAPHS, 256>>>(bufB);
    mlp_kernel<<<N_GRAPHS, HID>>>(x_scalar, Wl1, bl1, Wl2, bl2, out);
}

// round 11
// speedup vs baseline: 2.8743x; 1.3440x over previous
#include <cuda_runtime.h>
#include <cuda_fp16.h>
#include <cstdint>

#define N_NODES  50000
#define N_EDGES  400000
#define N_GRAPHS 500
#define N_FEAT   4
#define EMB      200
#define HID      128

// padded GEMM dims
#define KPAD 208            // K padded (13 chunks of 16)
#define NPAD 208            // N padded
#define NKP  (KPAD / 2)     // 104 k-pairs

// ---------------- device scratch (no runtime allocation allowed) ----------
__device__ __half g_bufA[(size_t)N_NODES * EMB];
__device__ __half g_bufB[(size_t)N_NODES * EMB];
__device__ __half g_hw  [(size_t)N_NODES * EMB];
__device__ float  g_aggx[(size_t)N_NODES * 4];
__device__ float g_dinv[N_NODES];
__device__ int   g_deg [N_NODES];
__device__ int   g_off [N_NODES + 1];
__device__ int   g_cur [N_NODES];
__device__ int   g_csr_src [N_EDGES];
__device__ float g_csr_coef[N_EDGES];
__device__ int   g_flag_ei;
__device__ int   g_flag_bi;
__device__ float g_pool[N_GRAPHS * EMB];
__device__ int   g_gcnt[N_GRAPHS];
__device__ int   g_goff[N_GRAPHS];
__device__ int   g_part [64];
__device__ int   g_pscan[64];
// packed fp16 hi/lo splits of W1..W3: [layer][kpair][n] as (f16 k, f16 k+1)
__device__ uint32_t g_Whi[3][NKP * NPAD];
__device__ uint32_t g_Wlo[3][NKP * NPAD];

// ---------------- dtype detection ----------------------------------------
__global__ void detect_kernel(const void* ei, const void* bi) {
    if (threadIdx.x == 0 && blockIdx.x == 0) {
        const int* e32 = (const int*)ei;
        int all0 = 1;
        for (int i = 0; i < 16; i++) if (e32[2 * i + 1] != 0) all0 = 0;
        g_flag_ei = all0;
        const int* b32 = (const int*)bi;
        int all0b = 1;
        for (int i = 0; i < 16; i++) if (b32[2 * (20000 + i) + 1] != 0) all0b = 0;
        g_flag_bi = all0b;
    }
}

__device__ __forceinline__ int ld_idx(const void* p, long long i, int is64) {
    if (is64) return (int)((const long long*)p)[i];
    return ((const int*)p)[i];
}

// ---------------- graph preprocessing -------------------------------------
__global__ void init_kernel() {
    int i = blockIdx.x * blockDim.x + threadIdx.x;
    if (i < N_NODES) { g_deg[i] = 0; g_cur[i] = 0; }
    if (i < N_GRAPHS) g_gcnt[i] = 0;
}

__global__ void count_kernel(const void* ei, const void* bi) {
    int e = blockIdx.x * blockDim.x + threadIdx.x;
    if (e < N_EDGES) {
        int d = ld_idx(ei, (long long)N_EDGES + e, g_flag_ei);
        atomicAdd(&g_deg[d], 1);
    }
    if (e < N_NODES) {
        int b = ld_idx(bi, e, g_flag_bi);
        atomicAdd(&g_gcnt[b], 1);
    }
}

#define SCAN_B 1024
#define SCAN_NB ((N_NODES + SCAN_B - 1) / SCAN_B)   // 49

__global__ void scan_part_kernel() {
    __shared__ int ws[32];
    int i = blockIdx.x * SCAN_B + threadIdx.x;
    int v = (i < N_NODES) ? g_deg[i] : 0;
#pragma unroll
    for (int d = 16; d; d >>= 1) v += __shfl_down_sync(0xffffffffu, v, d);
    if ((threadIdx.x & 31) == 0) ws[threadIdx.x >> 5] = v;
    __syncthreads();
    if (threadIdx.x < 32) {
        int s = ws[threadIdx.x];
#pragma unroll
        for (int d = 16; d; d >>= 1) s += __shfl_down_sync(0xffffffffu, s, d);
        if (threadIdx.x == 0) g_part[blockIdx.x] = s;
    }
}

__global__ void scan_top_kernel() {
    __shared__ int s[64];
    __shared__ int sg[512];
    int t = threadIdx.x;
    if (t < 64) {
        int v = (t < SCAN_NB) ? g_part[t] : 0;
        s[t] = v;
    }
    sg[t] = (t < N_GRAPHS) ? g_gcnt[t] : 0;
    __syncthreads();
    for (int d = 1; d < 64; d <<= 1) {
        int u = 0;
        if (t < 64 && t >= d) u = s[t - d];
        __syncthreads();
        if (t < 64 && t >= d) s[t] += u;
        __syncthreads();
    }
    for (int d = 1; d < 512; d <<= 1) {
        int u = 0;
        if (t >= d) u = sg[t - d];
        __syncthreads();
        if (t >= d) sg[t] += u;
        __syncthreads();
    }
    if (t < SCAN_NB) g_pscan[t] = s[t] - g_part[t];
    if (t == 0) g_off[N_NODES] = N_EDGES;
    if (t < N_GRAPHS) g_goff[t] = (t == 0) ? 0 : sg[t - 1];
}

__global__ void scan_final_kernel() {
    __shared__ int wsum[32];
    int tid = threadIdx.x, lane = tid & 31, wid = tid >> 5;
    int i = blockIdx.x * SCAN_B + tid;
    int v = (i < N_NODES) ? g_deg[i] : 0;
    int inc = v;
#pragma unroll
    for (int d = 1; d < 32; d <<= 1) {
        int u = __shfl_up_sync(0xffffffffu, inc, d);
        if (lane >= d) inc += u;
    }
    if (lane == 31) wsum[wid] = inc;
    __syncthreads();
    if (wid == 0) {
        int s = wsum[lane];
        int si = s;
#pragma unroll
        for (int d = 1; d < 32; d <<= 1) {
            int u = __shfl_up_sync(0xffffffffu, si, d);
            if (lane >= d) si += u;
        }
        wsum[lane] = si - s;
    }
    __syncthreads();
    if (i < N_NODES) {
        g_off[i]  = g_pscan[blockIdx.x] + wsum[wid] + (inc - v);
        g_dinv[i] = rsqrtf((float)(v + 1));
    }
}

__global__ void scatter_kernel(const void* ei) {
    int e = blockIdx.x * blockDim.x + threadIdx.x;
    if (e >= N_EDGES) return;
    int is64 = g_flag_ei;
    int s = ld_idx(ei, e, is64);
    int d = ld_idx(ei, (long long)N_EDGES + e, is64);
    int p = g_off[d] + atomicAdd(&g_cur[d], 1);
    g_csr_src[p]  = s;
    g_csr_coef[p] = g_dinv[s] * g_dinv[d];
}

// ---------------- W split precompute (fp16 hi/lo) --------------------------
__device__ __forceinline__ uint32_t pack_h2(__half lo, __half hi) {
    uint16_t a = __half_as_ushort(lo);
    uint16_t b = __half_as_ushort(hi);
    return (uint32_t)a | ((uint32_t)b << 16);
}

__global__ void split_w_kernel(const float* __restrict__ W1,
                               const float* __restrict__ W2,
                               const float* __restrict__ W3) {
    int idx = blockIdx.x * blockDim.x + threadIdx.x;
    int total = NKP * NPAD;
    if (idx >= 3 * total) return;
    int l = idx / total;
    int r = idx - l * total;
    int kp = r / NPAD, n = r - kp * NPAD;
    const float* W = (l == 0) ? W1 : (l == 1) ? W2 : W3;
    int k0 = 2 * kp, k1 = 2 * kp + 1;
    float w0 = (k0 < EMB && n < EMB) ? W[k0 * EMB + n] : 0.f;
    float w1 = (k1 < EMB && n < EMB) ? W[k1 * EMB + n] : 0.f;
    __half h0 = __float2half_rn(w0);
    __half h1 = __float2half_rn(w1);
    __half l0 = __float2half_rn(w0 - __half2float(h0));
    __half l1 = __float2half_rn(w1 - __half2float(h1));
    g_Whi[l][r] = pack_h2(h0, h1);   // low 16 bits = even k
    g_Wlo[l][r] = pack_h2(l0, l1);
}

// ---------------- layer 0: aggregate(x) then (Ax)@W0 (linearity) -----------
__global__ void aggregate4_kernel(const float* __restrict__ x,
                                  float* __restrict__ outx) {
    int i = blockIdx.x * blockDim.x + threadIdx.x;
    if (i >= N_NODES) return;
    float dv = g_dinv[i];
    float selfc = dv * dv;
    float4 xi = *reinterpret_cast<const float4*>(x + (size_t)i * 4);
    float4 a = make_float4(selfc * xi.x, selfc * xi.y, selfc * xi.z, selfc * xi.w);
    int e0 = g_off[i], e1 = g_off[i + 1];
    for (int e = e0; e < e1; e++) {
        int s = g_csr_src[e];
        float c = g_csr_coef[e];
        float4 v = *reinterpret_cast<const float4*>(x + (size_t)s * 4);
        a.x += c * v.x; a.y += c * v.y; a.z += c * v.z; a.w += c * v.w;
    }
    *reinterpret_cast<float4*>(outx + (size_t)i * 4) = a;
}

// thread per output PAIR; writes fp16
__global__ void gemm0f_kernel(const float* __restrict__ xa,
                              const float* __restrict__ W0,
                              const float* __restrict__ b0,
                              __half* __restrict__ out) {
    int idx = blockIdx.x * blockDim.x + threadIdx.x;
    if (idx >= N_NODES * (EMB / 2)) return;
    int i = idx / (EMB / 2), p = idx - i * (EMB / 2);
    int f0 = 2 * p;
    const float* xr = xa + (size_t)i * 4;
    float x0 = xr[0], x1 = xr[1], x2 = xr[2], x3 = xr[3];
    float s0 = x0 * __ldg(&W0[f0])
             + x1 * __ldg(&W0[EMB + f0])
             + x2 * __ldg(&W0[2 * EMB + f0])
             + x3 * __ldg(&W0[3 * EMB + f0])
             + __ldg(&b0[f0]);
    float s1 = x0 * __ldg(&W0[f0 + 1])
             + x1 * __ldg(&W0[EMB + f0 + 1])
             + x2 * __ldg(&W0[2 * EMB + f0 + 1])
             + x3 * __ldg(&W0[3 * EMB + f0 + 1])
             + __ldg(&b0[f0 + 1]);
    s0 = s0 > 0.f ? s0 : 0.01f * s0;
    s1 = s1 > 0.f ? s1 : 0.01f * s1;
    __half2 o = __floats2half2_rn(s0, s1);
    *reinterpret_cast<__half2*>(&out[(size_t)i * EMB + f0]) = o;
}

// ---------------- layers 1-3: fp16x2 split GEMM via mma.sync.m16n8k16 ------
// A exact fp16 (no split); W = Whi + Wlo (fp16 pair). 2 MMAs per tile.
// block tile 64x208, 4 warps (2M x 2N), warp tile 32x104, double-buffered.
#define GBM   64
#define ASTR  12     // A smem row stride in words
#define BSTR  216    // B smem row stride in words

#define MMA_F16(d, a0, a1, a2, a3, b0, b1)                                    \
    asm volatile("mma.sync.aligned.m16n8k16.row.col.f32.f16.f16.f32 "        \
                 "{%0,%1,%2,%3}, {%4,%5,%6,%7}, {%8,%9}, {%0,%1,%2,%3};"     \
                 : "+f"((d)[0]), "+f"((d)[1]), "+f"((d)[2]), "+f"((d)[3])    \
                 : "r"(a0), "r"(a1), "r"(a2), "r"(a3), "r"(b0), "r"(b1))

__global__ __launch_bounds__(128) void gemm_f16x2_kernel(
    const __half* __restrict__ h,
    const uint32_t* __restrict__ whi, const uint32_t* __restrict__ wlo,
    __half* __restrict__ out) {
    __shared__ uint32_t sA [2][GBM * ASTR];
    __shared__ uint32_t sBh[2][8 * BSTR];
    __shared__ uint32_t sBl[2][8 * BSTR];

    int tid  = threadIdx.x;
    int lane = tid & 31, warp = tid >> 5;   // 4 warps
    int wm = warp >> 1;                     // 0..1
    int wn = warp & 1;                      // 0..1
    int row0 = blockIdx.x * GBM;
    int gid = lane >> 2;                    // 0..7
    int tig = lane & 3;                     // 0..3

    float acc[13][2][4];
#pragma unroll
    for (int t = 0; t < 13; t++)
#pragma unroll
        for (int f = 0; f < 2; f++) {
            acc[t][f][0] = 0.f; acc[t][f][1] = 0.f;
            acc[t][f][2] = 0.f; acc[t][f][3] = 0.f;
        }

    uint32_t ra[4];
    uint32_t rbh[13], rbl[13];

    auto FETCH = [&](int chunk) {
        int k0 = chunk * 16;
#pragma unroll
        for (int i = 0; i < 4; i++) {
            int idx = tid + i * 128;          // 0..511
            int r = idx >> 3, kp = idx & 7;
            int gr = row0 + r;
            int ka = k0 + 2 * kp;
            ra[i] = (gr < N_NODES && ka < EMB)
                  ? __ldg(reinterpret_cast<const uint32_t*>(h + (size_t)gr * EMB + ka))
                  : 0u;
        }
        int base = chunk * 8 * NPAD;
#pragma unroll
        for (int i = 0; i < 13; i++) {
            int idx = tid + i * 128;
            int r = idx / NPAD, c = idx - r * NPAD;
            int g = base + r * NPAD + c;
            rbh[i] = __ldg(&whi[g]);
            rbl[i] = __ldg(&wlo[g]);
        }
    };
    auto STORE = [&](int buf) {
#pragma unroll
        for (int i = 0; i < 4; i++) {
            int idx = tid + i * 128;
            int r = idx >> 3, kp = idx & 7;
            sA[buf][r * ASTR + kp] = ra[i];
        }
#pragma unroll
        for (int i = 0; i < 13; i++) {
            int idx = tid + i * 128;
            int r = idx / NPAD, c = idx - r * NPAD;
            sBh[buf][r * BSTR + c] = rbh[i];
            sBl[buf][r * BSTR + c] = rbl[i];
        }
    };

    FETCH(0);
    STORE(0);
    __syncthreads();

    int ar = wm * 32 + gid;
#pragma unroll 1
    for (int ks = 0; ks < 13; ks++) {
        int cur = ks & 1;
        if (ks < 12) FETCH(ks + 1);

        uint32_t a[8];
#pragma unroll
        for (int f = 0; f < 2; f++) {
            int r = ar + f * 16;
            a[f * 4 + 0] = sA[cur][r * ASTR + tig];
            a[f * 4 + 1] = sA[cur][(r + 8) * ASTR + tig];
            a[f * 4 + 2] = sA[cur][r * ASTR + tig + 4];
            a[f * 4 + 3] = sA[cur][(r + 8) * ASTR + tig + 4];
        }

#pragma unroll
        for (int t = 0; t < 13; t++) {
            int n = wn * 104 + t * 8 + gid;
            uint32_t bh0 = sBh[cur][tig * BSTR + n];
            uint32_t bh1 = sBh[cur][(tig + 4) * BSTR + n];
            uint32_t bl0 = sBl[cur][tig * BSTR + n];
            uint32_t bl1 = sBl[cur][(tig + 4) * BSTR + n];
            MMA_F16(acc[t][0], a[0], a[1], a[2], a[3], bh0, bh1);
            MMA_F16(acc[t][1], a[4], a[5], a[6], a[7], bh0, bh1);
            MMA_F16(acc[t][0], a[0], a[1], a[2], a[3], bl0, bl1);
            MMA_F16(acc[t][1], a[4], a[5], a[6], a[7], bl0, bl1);
        }

        if (ks < 12) STORE(cur ^ 1);
        __syncthreads();
    }

#pragma unroll
    for (int t = 0; t < 13; t++) {
        int n = wn * 104 + t * 8 + 2 * tig;
        if (n >= EMB) continue;
#pragma unroll
        for (int f = 0; f < 2; f++) {
            int r = row0 + wm * 32 + f * 16 + gid;
            if (r < N_NODES) {
                __half2 v = __floats2half2_rn(acc[t][f][0], acc[t][f][1]);
                *reinterpret_cast<__half2*>(&out[(size_t)r * EMB + n]) = v;
            }
            if (r + 8 < N_NODES) {
                __half2 v = __floats2half2_rn(acc[t][f][2], acc[t][f][3]);
                *reinterpret_cast<__half2*>(&out[(size_t)(r + 8) * EMB + n]) = v;
            }
        }
    }
}

// ---------------- edge aggregation (fp16 gather, warp per dst node) --------
// row = 200 fp16 = 400B = 25 x uint4; lanes 0..24 each own 8 features.
__device__ __forceinline__ void unpack8(uint4 v, float* f) {
    float2 t;
    t = __half22float2(*reinterpret_cast<__half2*>(&v.x)); f[0] = t.x; f[1] = t.y;
    t = __half22float2(*reinterpret_cast<__half2*>(&v.y)); f[2] = t.x; f[3] = t.y;
    t = __half22float2(*reinterpret_cast<__half2*>(&v.z)); f[4] = t.x; f[5] = t.y;
    t = __half22float2(*reinterpret_cast<__half2*>(&v.w)); f[6] = t.x; f[7] = t.y;
}

__global__ __launch_bounds__(256) void aggregate_h_kernel(
    const __half* __restrict__ hw, const float* __restrict__ b,
    __half* __restrict__ out) {
    int warp = (blockIdx.x * blockDim.x + threadIdx.x) >> 5;
    int lane = threadIdx.x & 31;
    if (warp >= N_NODES || lane >= 25) return;
    int i = warp;

    float dv = g_dinv[i];
    float selfc = dv * dv;

    const uint4* h4 = reinterpret_cast<const uint4*>(hw);
    float acc[8], f[8];
    {
        uint4 v = __ldg(&h4[(size_t)i * 25 + lane]);
        unpack8(v, f);
#pragma unroll
        for (int j = 0; j < 8; j++) acc[j] = selfc * f[j];
    }

    int e0 = g_off[i], e1 = g_off[i + 1];
    for (int e = e0; e < e1; e++) {
        int   s = g_csr_src[e];
        float c = g_csr_coef[e];
        uint4 v = __ldg(&h4[(size_t)s * 25 + lane]);
        unpack8(v, f);
#pragma unroll
        for (int j = 0; j < 8; j++) acc[j] += c * f[j];
    }

    int f0 = lane * 8;
    float4 b0 = *reinterpret_cast<const float4*>(b + f0);
    float4 b1 = *reinterpret_cast<const float4*>(b + f0 + 4);
    acc[0] += b0.x; acc[1] += b0.y; acc[2] += b0.z; acc[3] += b0.w;
    acc[4] += b1.x; acc[5] += b1.y; acc[6] += b1.z; acc[7] += b1.w;
#pragma unroll
    for (int j = 0; j < 8; j++) acc[j] = acc[j] > 0.f ? acc[j] : 0.01f * acc[j];

    uint4 pv;
    __half2 p;
    p = __floats2half2_rn(acc[0], acc[1]); pv.x = *reinterpret_cast<uint32_t*>(&p);
    p = __floats2half2_rn(acc[2], acc[3]); pv.y = *reinterpret_cast<uint32_t*>(&p);
    p = __floats2half2_rn(acc[4], acc[5]); pv.z = *reinterpret_cast<uint32_t*>(&p);
    p = __floats2half2_rn(acc[6], acc[7]); pv.w = *reinterpret_cast<uint32_t*>(&p);
    reinterpret_cast<uint4*>(out)[(size_t)i * 25 + lane] = pv;
}

// ---------------- pooling + MLP head ---------------------------------------
__global__ void pool_kernel(const __half* __restrict__ h) {
    int g = blockIdx.x;
    int t = threadIdx.x;
    if (t >= EMB) return;
    int r0 = g_goff[g];
    int n = g_gcnt[g];
    float s = 0.f;
    for (int j = 0; j < n; j++) s += __half2float(h[(size_t)(r0 + j) * EMB + t]);
    g_pool[g * EMB + t] = s / fmaxf((float)n, 1.0f);
}

__global__ __launch_bounds__(HID) void mlp_kernel(
    const float* __restrict__ xs,
    const float* __restrict__ Wl1, const float* __restrict__ bl1,
    const float* __restrict__ Wl2, const float* __restrict__ bl2,
    float* __restrict__ out) {
    int g = blockIdx.x;
    int t = threadIdx.x;
    __shared__ float gv[EMB + N_FEAT];
    __shared__ float red[HID];

    for (int k = t; k < EMB; k += HID) gv[k] = g_pool[g * EMB + k];
    if (t < N_FEAT) gv[EMB + t] = xs[g * N_FEAT + t];
    __syncthreads();

    float acc = bl1[t];
    for (int k = 0; k < EMB + N_FEAT; k++) acc += gv[k] * Wl1[k * HID + t];
    acc = acc > 0.f ? acc : 0.01f * acc;
    red[t] = acc * Wl2[t];
    __syncthreads();
    for (int s = HID / 2; s > 0; s >>= 1) {
        if (t < s) red[t] += red[t + s];
        __syncthreads();
    }
    if (t == 0) out[g] = red[0] + bl2[0];
}

// ---------------- launcher --------------------------------------------------
extern "C" void kernel_launch(void* const* d_in, const int* in_sizes, int n_in,
                              void* d_out, int out_size) {
    const float* x        = (const float*)d_in[0];
    const void*  ei       = d_in[1];
    const float* x_scalar = (const float*)d_in[2];
    const void*  bi       = d_in[3];
    const float* W0  = (const float*)d_in[4];
    const float* b0  = (const float*)d_in[5];
    const float* W1  = (const float*)d_in[6];
    const float* b1  = (const float*)d_in[7];
    const float* W2  = (const float*)d_in[8];
    const float* b2  = (const float*)d_in[9];
    const float* W3  = (const float*)d_in[10];
    const float* b3  = (const float*)d_in[11];
    const float* Wl1 = (const float*)d_in[12];
    const float* bl1 = (const float*)d_in[13];
    const float* Wl2 = (const float*)d_in[14];
    const float* bl2 = (const float*)d_in[15];
    float* out = (float*)d_out;

    __half *bufA, *bufB, *hw;
    float* aggx;
    uint32_t *whi, *wlo;
    cudaGetSymbolAddress((void**)&bufA, g_bufA);
    cudaGetSymbolAddress((void**)&bufB, g_bufB);
    cudaGetSymbolAddress((void**)&hw,   g_hw);
    cudaGetSymbolAddress((void**)&aggx, g_aggx);
    cudaGetSymbolAddress((void**)&whi,  g_Whi);
    cudaGetSymbolAddress((void**)&wlo,  g_Wlo);

    const int TB = 256;
    int gridN  = (N_NODES + TB - 1) / TB;
    int gridE  = (N_EDGES + TB - 1) / TB;
    int gridG0 = (N_NODES * (EMB / 2) + TB - 1) / TB;
    int gridAg = (N_NODES * 32 + TB - 1) / TB;
    int gridGm = (N_NODES + GBM - 1) / GBM;            // 782
    int gridW  = (3 * NKP * NPAD + TB - 1) / TB;

    // preprocessing (8 launches)
    detect_kernel<<<1, 32>>>(ei, bi);
    init_kernel<<<gridN, TB>>>();
    split_w_kernel<<<gridW, TB>>>(W1, W2, W3);
    count_kernel<<<gridE, TB>>>(ei, bi);
    scan_part_kernel<<<SCAN_NB, SCAN_B>>>();
    scan_top_kernel<<<1, 512>>>();
    scan_final_kernel<<<SCAN_NB, SCAN_B>>>();
    scatter_kernel<<<gridE, TB>>>(ei);

    const int WTOT = NKP * NPAD;

    // layer 0 (aggregate-first by linearity; bias+leaky fused into gemm0f)
    aggregate4_kernel<<<gridN, TB>>>(x, aggx);
    gemm0f_kernel<<<gridG0, TB>>>(aggx, W0, b0, bufA);

    // layer 1
    gemm_f16x2_kernel<<<gridGm, 128>>>(bufA, whi, wlo, hw);
    aggregate_h_kernel<<<gridAg, TB>>>(hw, b1, bufB);
    // layer 2
    gemm_f16x2_kernel<<<gridGm, 128>>>(bufB, whi + WTOT, wlo + WTOT, hw);
    aggregate_h_kernel<<<gridAg, TB>>>(hw, b2, bufA);
    // layer 3
    gemm_f16x2_kernel<<<gridGm, 128>>>(bufA, whi + 2 * WTOT, wlo + 2 * WTOT, hw);
    aggregate_h_kernel<<<gridAg, TB>>>(hw, b3, bufB);

    // pool + MLP head
    pool_kernel<<<N_GRAPHS, 256>>>(bufB);
    mlp_kernel<<<N_GRAPHS, HID>>>(x_scalar, Wl1, bl1, Wl2, bl2, out);
}

// round 12
// speedup vs baseline: 2.8758x; 1.0005x over previous
#include <cuda_runtime.h>
#include <cuda_fp16.h>
#include <cstdint>

#define N_NODES  50000
#define N_EDGES  400000
#define N_GRAPHS 500
#define N_FEAT   4
#define EMB      200
#define HID      128

// padded GEMM dims
#define KPAD 208            // K padded (13 chunks of 16)
#define NPAD 208            // N padded
#define NKP  (KPAD / 2)     // 104 k-pairs

// ---------------- device scratch (no runtime allocation allowed) ----------
__device__ __half g_bufA[(size_t)N_NODES * EMB];
__device__ __half g_bufB[(size_t)N_NODES * EMB];
__device__ __half g_hw  [(size_t)N_NODES * EMB];
__device__ float  g_aggx[(size_t)N_NODES * 4];
__device__ float g_dinv[N_NODES];
__device__ int   g_deg [N_NODES];
__device__ int   g_off [N_NODES + 1];
__device__ int   g_cur [N_NODES];
__device__ int   g_csr_src [N_EDGES];
__device__ float g_csr_coef[N_EDGES];
__device__ int   g_flag_ei;
__device__ int   g_flag_bi;
__device__ float g_pool[N_GRAPHS * EMB];
__device__ int   g_gcnt[N_GRAPHS];
__device__ int   g_goff[N_GRAPHS];
__device__ int   g_part [64];
__device__ int   g_pscan[64];
// packed fp16 hi/lo splits of W1..W3: [layer][kpair][n] as (f16 k, f16 k+1)
__device__ uint32_t g_Whi[3][NKP * NPAD];
__device__ uint32_t g_Wlo[3][NKP * NPAD];

// ---------------- dtype detection ----------------------------------------
__global__ void detect_kernel(const void* ei, const void* bi) {
    if (threadIdx.x == 0 && blockIdx.x == 0) {
        const int* e32 = (const int*)ei;
        int all0 = 1;
        for (int i = 0; i < 16; i++) if (e32[2 * i + 1] != 0) all0 = 0;
        g_flag_ei = all0;
        const int* b32 = (const int*)bi;
        int all0b = 1;
        for (int i = 0; i < 16; i++) if (b32[2 * (20000 + i) + 1] != 0) all0b = 0;
        g_flag_bi = all0b;
    }
}

__device__ __forceinline__ int ld_idx(const void* p, long long i, int is64) {
    if (is64) return (int)((const long long*)p)[i];
    return ((const int*)p)[i];
}

// ---------------- graph preprocessing -------------------------------------
__global__ void init_kernel() {
    int i = blockIdx.x * blockDim.x + threadIdx.x;
    if (i < N_NODES) { g_deg[i] = 0; g_cur[i] = 0; }
    if (i < N_GRAPHS) g_gcnt[i] = 0;
}

__global__ void count_kernel(const void* ei, const void* bi) {
    int e = blockIdx.x * blockDim.x + threadIdx.x;
    if (e < N_EDGES) {
        int d = ld_idx(ei, (long long)N_EDGES + e, g_flag_ei);
        atomicAdd(&g_deg[d], 1);
    }
    if (e < N_NODES) {
        int b = ld_idx(bi, e, g_flag_bi);
        atomicAdd(&g_gcnt[b], 1);
    }
}

#define SCAN_B 1024
#define SCAN_NB ((N_NODES + SCAN_B - 1) / SCAN_B)   // 49

__global__ void scan_part_kernel() {
    __shared__ int ws[32];
    int i = blockIdx.x * SCAN_B + threadIdx.x;
    int v = (i < N_NODES) ? g_deg[i] : 0;
#pragma unroll
    for (int d = 16; d; d >>= 1) v += __shfl_down_sync(0xffffffffu, v, d);
    if ((threadIdx.x & 31) == 0) ws[threadIdx.x >> 5] = v;
    __syncthreads();
    if (threadIdx.x < 32) {
        int s = ws[threadIdx.x];
#pragma unroll
        for (int d = 16; d; d >>= 1) s += __shfl_down_sync(0xffffffffu, s, d);
        if (threadIdx.x == 0) g_part[blockIdx.x] = s;
    }
}

__global__ void scan_top_kernel() {
    __shared__ int s[64];
    __shared__ int sg[512];
    int t = threadIdx.x;
    if (t < 64) {
        int v = (t < SCAN_NB) ? g_part[t] : 0;
        s[t] = v;
    }
    sg[t] = (t < N_GRAPHS) ? g_gcnt[t] : 0;
    __syncthreads();
    for (int d = 1; d < 64; d <<= 1) {
        int u = 0;
        if (t < 64 && t >= d) u = s[t - d];
        __syncthreads();
        if (t < 64 && t >= d) s[t] += u;
        __syncthreads();
    }
    for (int d = 1; d < 512; d <<= 1) {
        int u = 0;
        if (t >= d) u = sg[t - d];
        __syncthreads();
        if (t >= d) sg[t] += u;
        __syncthreads();
    }
    if (t < SCAN_NB) g_pscan[t] = s[t] - g_part[t];
    if (t == 0) g_off[N_NODES] = N_EDGES;
    if (t < N_GRAPHS) g_goff[t] = (t == 0) ? 0 : sg[t - 1];
}

__global__ void scan_final_kernel() {
    __shared__ int wsum[32];
    int tid = threadIdx.x, lane = tid & 31, wid = tid >> 5;
    int i = blockIdx.x * SCAN_B + tid;
    int v = (i < N_NODES) ? g_deg[i] : 0;
    int inc = v;
#pragma unroll
    for (int d = 1; d < 32; d <<= 1) {
        int u = __shfl_up_sync(0xffffffffu, inc, d);
        if (lane >= d) inc += u;
    }
    if (lane == 31) wsum[wid] = inc;
    __syncthreads();
    if (wid == 0) {
        int s = wsum[lane];
        int si = s;
#pragma unroll
        for (int d = 1; d < 32; d <<= 1) {
            int u = __shfl_up_sync(0xffffffffu, si, d);
            if (lane >= d) si += u;
        }
        wsum[lane] = si - s;
    }
    __syncthreads();
    if (i < N_NODES) {
        g_off[i]  = g_pscan[blockIdx.x] + wsum[wid] + (inc - v);
        g_dinv[i] = rsqrtf((float)(v + 1));
    }
}

__global__ void scatter_kernel(const void* ei) {
    int e = blockIdx.x * blockDim.x + threadIdx.x;
    if (e >= N_EDGES) return;
    int is64 = g_flag_ei;
    int s = ld_idx(ei, e, is64);
    int d = ld_idx(ei, (long long)N_EDGES + e, is64);
    int p = g_off[d] + atomicAdd(&g_cur[d], 1);
    g_csr_src[p]  = s;
    g_csr_coef[p] = g_dinv[s] * g_dinv[d];
}

// ---------------- W split precompute (fp16 hi/lo) --------------------------
__device__ __forceinline__ uint32_t pack_h2(__half lo, __half hi) {
    uint16_t a = __half_as_ushort(lo);
    uint16_t b = __half_as_ushort(hi);
    return (uint32_t)a | ((uint32_t)b << 16);
}

__global__ void split_w_kernel(const float* __restrict__ W1,
                               const float* __restrict__ W2,
                               const float* __restrict__ W3) {
    int idx = blockIdx.x * blockDim.x + threadIdx.x;
    int total = NKP * NPAD;
    if (idx >= 3 * total) return;
    int l = idx / total;
    int r = idx - l * total;
    int kp = r / NPAD, n = r - kp * NPAD;
    const float* W = (l == 0) ? W1 : (l == 1) ? W2 : W3;
    int k0 = 2 * kp, k1 = 2 * kp + 1;
    float w0 = (k0 < EMB && n < EMB) ? W[k0 * EMB + n] : 0.f;
    float w1 = (k1 < EMB && n < EMB) ? W[k1 * EMB + n] : 0.f;
    __half h0 = __float2half_rn(w0);
    __half h1 = __float2half_rn(w1);
    __half l0 = __float2half_rn(w0 - __half2float(h0));
    __half l1 = __float2half_rn(w1 - __half2float(h1));
    g_Whi[l][r] = pack_h2(h0, h1);   // low 16 bits = even k
    g_Wlo[l][r] = pack_h2(l0, l1);
}

// ---------------- layer 0: aggregate(x) then (Ax)@W0 (linearity) -----------
__global__ void aggregate4_kernel(const float* __restrict__ x,
                                  float* __restrict__ outx) {
    int i = blockIdx.x * blockDim.x + threadIdx.x;
    if (i >= N_NODES) return;
    float dv = g_dinv[i];
    float selfc = dv * dv;
    float4 xi = *reinterpret_cast<const float4*>(x + (size_t)i * 4);
    float4 a = make_float4(selfc * xi.x, selfc * xi.y, selfc * xi.z, selfc * xi.w);
    int e0 = g_off[i], e1 = g_off[i + 1];
    for (int e = e0; e < e1; e++) {
        int s = g_csr_src[e];
        float c = g_csr_coef[e];
        float4 v = *reinterpret_cast<const float4*>(x + (size_t)s * 4);
        a.x += c * v.x; a.y += c * v.y; a.z += c * v.z; a.w += c * v.w;
    }
    *reinterpret_cast<float4*>(outx + (size_t)i * 4) = a;
}

// thread per output PAIR; writes fp16
__global__ void gemm0f_kernel(const float* __restrict__ xa,
                              const float* __restrict__ W0,
                              const float* __restrict__ b0,
                              __half* __restrict__ out) {
    int idx = blockIdx.x * blockDim.x + threadIdx.x;
    if (idx >= N_NODES * (EMB / 2)) return;
    int i = idx / (EMB / 2), p = idx - i * (EMB / 2);
    int f0 = 2 * p;
    const float* xr = xa + (size_t)i * 4;
    float x0 = xr[0], x1 = xr[1], x2 = xr[2], x3 = xr[3];
    float s0 = x0 * __ldg(&W0[f0])
             + x1 * __ldg(&W0[EMB + f0])
             + x2 * __ldg(&W0[2 * EMB + f0])
             + x3 * __ldg(&W0[3 * EMB + f0])
             + __ldg(&b0[f0]);
    float s1 = x0 * __ldg(&W0[f0 + 1])
             + x1 * __ldg(&W0[EMB + f0 + 1])
             + x2 * __ldg(&W0[2 * EMB + f0 + 1])
             + x3 * __ldg(&W0[3 * EMB + f0 + 1])
             + __ldg(&b0[f0 + 1]);
    s0 = s0 > 0.f ? s0 : 0.01f * s0;
    s1 = s1 > 0.f ? s1 : 0.01f * s1;
    __half2 o = __floats2half2_rn(s0, s1);
    *reinterpret_cast<__half2*>(&out[(size_t)i * EMB + f0]) = o;
}

// ---------------- layers 1-3: fp16x2 split GEMM via mma.sync.m16n8k16 ------
// A exact fp16 (no split); W = Whi + Wlo (fp16 pair). 2 MMAs per tile.
// block tile 64x208, 4 warps (2M x 2N), warp tile 32x104, double-buffered.
#define GBM   64
#define ASTR  12     // A smem row stride in words
#define BSTR  216    // B smem row stride in words

#define MMA_F16(d, a0, a1, a2, a3, b0, b1)                                    \
    asm volatile("mma.sync.aligned.m16n8k16.row.col.f32.f16.f16.f32 "        \
                 "{%0,%1,%2,%3}, {%4,%5,%6,%7}, {%8,%9}, {%0,%1,%2,%3};"     \
                 : "+f"((d)[0]), "+f"((d)[1]), "+f"((d)[2]), "+f"((d)[3])    \
                 : "r"(a0), "r"(a1), "r"(a2), "r"(a3), "r"(b0), "r"(b1))

__global__ __launch_bounds__(128) void gemm_f16x2_kernel(
    const __half* __restrict__ h,
    const uint32_t* __restrict__ whi, const uint32_t* __restrict__ wlo,
    __half* __restrict__ out) {
    __shared__ uint32_t sA [2][GBM * ASTR];
    __shared__ uint32_t sBh[2][8 * BSTR];
    __shared__ uint32_t sBl[2][8 * BSTR];

    int tid  = threadIdx.x;
    int lane = tid & 31, warp = tid >> 5;   // 4 warps
    int wm = warp >> 1;                     // 0..1
    int wn = warp & 1;                      // 0..1
    int row0 = blockIdx.x * GBM;
    int gid = lane >> 2;                    // 0..7
    int tig = lane & 3;                     // 0..3

    float acc[13][2][4];
#pragma unroll
    for (int t = 0; t < 13; t++)
#pragma unroll
        for (int f = 0; f < 2; f++) {
            acc[t][f][0] = 0.f; acc[t][f][1] = 0.f;
            acc[t][f][2] = 0.f; acc[t][f][3] = 0.f;
        }

    uint32_t ra[4];
    uint32_t rbh[13], rbl[13];

    auto FETCH = [&](int chunk) {
        int k0 = chunk * 16;
#pragma unroll
        for (int i = 0; i < 4; i++) {
            int idx = tid + i * 128;          // 0..511
            int r = idx >> 3, kp = idx & 7;
            int gr = row0 + r;
            int ka = k0 + 2 * kp;
            ra[i] = (gr < N_NODES && ka < EMB)
                  ? __ldg(reinterpret_cast<const uint32_t*>(h + (size_t)gr * EMB + ka))
                  : 0u;
        }
        int base = chunk * 8 * NPAD;
#pragma unroll
        for (int i = 0; i < 13; i++) {
            int idx = tid + i * 128;
            int r = idx / NPAD, c = idx - r * NPAD;
            int g = base + r * NPAD + c;
            rbh[i] = __ldg(&whi[g]);
            rbl[i] = __ldg(&wlo[g]);
        }
    };
    auto STORE = [&](int buf) {
#pragma unroll
        for (int i = 0; i < 4; i++) {
            int idx = tid + i * 128;
            int r = idx >> 3, kp = idx & 7;
            sA[buf][r * ASTR + kp] = ra[i];
        }
#pragma unroll
        for (int i = 0; i < 13; i++) {
            int idx = tid + i * 128;
            int r = idx / NPAD, c = idx - r * NPAD;
            sBh[buf][r * BSTR + c] = rbh[i];
            sBl[buf][r * BSTR + c] = rbl[i];
        }
    };

    FETCH(0);
    STORE(0);
    __syncthreads();

    int ar = wm * 32 + gid;
#pragma unroll 1
    for (int ks = 0; ks < 13; ks++) {
        int cur = ks & 1;
        if (ks < 12) FETCH(ks + 1);

        uint32_t a[8];
#pragma unroll
        for (int f = 0; f < 2; f++) {
            int r = ar + f * 16;
            a[f * 4 + 0] = sA[cur][r * ASTR + tig];
            a[f * 4 + 1] = sA[cur][(r + 8) * ASTR + tig];
            a[f * 4 + 2] = sA[cur][r * ASTR + tig + 4];
            a[f * 4 + 3] = sA[cur][(r + 8) * ASTR + tig + 4];
        }

#pragma unroll
        for (int t = 0; t < 13; t++) {
            int n = wn * 104 + t * 8 + gid;
            uint32_t bh0 = sBh[cur][tig * BSTR + n];
            uint32_t bh1 = sBh[cur][(tig + 4) * BSTR + n];
            uint32_t bl0 = sBl[cur][tig * BSTR + n];
            uint32_t bl1 = sBl[cur][(tig + 4) * BSTR + n];
            MMA_F16(acc[t][0], a[0], a[1], a[2], a[3], bh0, bh1);
            MMA_F16(acc[t][1], a[4], a[5], a[6], a[7], bh0, bh1);
            MMA_F16(acc[t][0], a[0], a[1], a[2], a[3], bl0, bl1);
            MMA_F16(acc[t][1], a[4], a[5], a[6], a[7], bl0, bl1);
        }

        if (ks < 12) STORE(cur ^ 1);
        __syncthreads();
    }

#pragma unroll
    for (int t = 0; t < 13; t++) {
        int n = wn * 104 + t * 8 + 2 * tig;
        if (n >= EMB) continue;
#pragma unroll
        for (int f = 0; f < 2; f++) {
            int r = row0 + wm * 32 + f * 16 + gid;
            if (r < N_NODES) {
                __half2 v = __floats2half2_rn(acc[t][f][0], acc[t][f][1]);
                *reinterpret_cast<__half2*>(&out[(size_t)r * EMB + n]) = v;
            }
            if (r + 8 < N_NODES) {
                __half2 v = __floats2half2_rn(acc[t][f][2], acc[t][f][3]);
                *reinterpret_cast<__half2*>(&out[(size_t)(r + 8) * EMB + n]) = v;
            }
        }
    }
}

// ---------------- edge aggregation (fp16 gather, warp per dst node) --------
// row = 200 fp16 = 400B = 25 x uint4; lanes 0..24 each own 8 features.
__device__ __forceinline__ void unpack8(uint4 v, float* f) {
    float2 t;
    t = __half22float2(*reinterpret_cast<__half2*>(&v.x)); f[0] = t.x; f[1] = t.y;
    t = __half22float2(*reinterpret_cast<__half2*>(&v.y)); f[2] = t.x; f[3] = t.y;
    t = __half22float2(*reinterpret_cast<__half2*>(&v.z)); f[4] = t.x; f[5] = t.y;
    t = __half22float2(*reinterpret_cast<__half2*>(&v.w)); f[6] = t.x; f[7] = t.y;
}

__global__ __launch_bounds__(256) void aggregate_h_kernel(
    const __half* __restrict__ hw, const float* __restrict__ b,
    __half* __restrict__ out) {
    int warp = (blockIdx.x * blockDim.x + threadIdx.x) >> 5;
    int lane = threadIdx.x & 31;
    if (warp >= N_NODES || lane >= 25) return;
    int i = warp;

    float dv = g_dinv[i];
    float selfc = dv * dv;

    const uint4* h4 = reinterpret_cast<const uint4*>(hw);
    float acc[8], f[8];
    {
        uint4 v = __ldg(&h4[(size_t)i * 25 + lane]);
        unpack8(v, f);
#pragma unroll
        for (int j = 0; j < 8; j++) acc[j] = selfc * f[j];
    }

    int e0 = g_off[i], e1 = g_off[i + 1];
    for (int e = e0; e < e1; e++) {
        int   s = g_csr_src[e];
        float c = g_csr_coef[e];
        uint4 v = __ldg(&h4[(size_t)s * 25 + lane]);
        unpack8(v, f);
#pragma unroll
        for (int j = 0; j < 8; j++) acc[j] += c * f[j];
    }

    int f0 = lane * 8;
    float4 b0 = *reinterpret_cast<const float4*>(b + f0);
    float4 b1 = *reinterpret_cast<const float4*>(b + f0 + 4);
    acc[0] += b0.x; acc[1] += b0.y; acc[2] += b0.z; acc[3] += b0.w;
    acc[4] += b1.x; acc[5] += b1.y; acc[6] += b1.z; acc[7] += b1.w;
#pragma unroll
    for (int j = 0; j < 8; j++) acc[j] = acc[j] > 0.f ? acc[j] : 0.01f * acc[j];

    uint4 pv;
    __half2 p;
    p = __floats2half2_rn(acc[0], acc[1]); pv.x = *reinterpret_cast<uint32_t*>(&p);
    p = __floats2half2_rn(acc[2], acc[3]); pv.y = *reinterpret_cast<uint32_t*>(&p);
    p = __floats2half2_rn(acc[4], acc[5]); pv.z = *reinterpret_cast<uint32_t*>(&p);
    p = __floats2half2_rn(acc[6], acc[7]); pv.w = *reinterpret_cast<uint32_t*>(&p);
    reinterpret_cast<uint4*>(out)[(size_t)i * 25 + lane] = pv;
}

// ---------------- pooling + MLP head ---------------------------------------
__global__ void pool_kernel(const __half* __restrict__ h) {
    int g = blockIdx.x;
    int t = threadIdx.x;
    if (t >= EMB) return;
    int r0 = g_goff[g];
    int n = g_gcnt[g];
    float s = 0.f;
    for (int j = 0; j < n; j++) s += __half2float(h[(size_t)(r0 + j) * EMB + t]);
    g_pool[g * EMB + t] = s / fmaxf((float)n, 1.0f);
}

__global__ __launch_bounds__(HID) void mlp_kernel(
    const float* __restrict__ xs,
    const float* __restrict__ Wl1, const float* __restrict__ bl1,
    const float* __restrict__ Wl2, const float* __restrict__ bl2,
    float* __restrict__ out) {
    int g = blockIdx.x;
    int t = threadIdx.x;
    __shared__ float gv[EMB + N_FEAT];
    __shared__ float red[HID];

    for (int k = t; k < EMB; k += HID) gv[k] = g_pool[g * EMB + k];
    if (t < N_FEAT) gv[EMB + t] = xs[g * N_FEAT + t];
    __syncthreads();

    float acc = bl1[t];
    for (int k = 0; k < EMB + N_FEAT; k++) acc += gv[k] * Wl1[k * HID + t];
    acc = acc > 0.f ? acc : 0.01f * acc;
    red[t] = acc * Wl2[t];
    __syncthreads();
    for (int s = HID / 2; s > 0; s >>= 1) {
        if (t < s) red[t] += red[t + s];
        __syncthreads();
    }
    if (t == 0) out[g] = red[0] + bl2[0];
}

// ---------------- launcher --------------------------------------------------
extern "C" void kernel_launch(void* const* d_in, const int* in_sizes, int n_in,
                              void* d_out, int out_size) {
    const float* x        = (const float*)d_in[0];
    const void*  ei       = d_in[1];
    const float* x_scalar = (const float*)d_in[2];
    const void*  bi       = d_in[3];
    const float* W0  = (const float*)d_in[4];
    const float* b0  = (const float*)d_in[5];
    const float* W1  = (const float*)d_in[6];
    const float* b1  = (const float*)d_in[7];
    const float* W2  = (const float*)d_in[8];
    const float* b2  = (const float*)d_in[9];
    const float* W3  = (const float*)d_in[10];
    const float* b3  = (const float*)d_in[11];
    const float* Wl1 = (const float*)d_in[12];
    const float* bl1 = (const float*)d_in[13];
    const float* Wl2 = (const float*)d_in[14];
    const float* bl2 = (const float*)d_in[15];
    float* out = (float*)d_out;

    __half *bufA, *bufB, *hw;
    float* aggx;
    uint32_t *whi, *wlo;
    cudaGetSymbolAddress((void**)&bufA, g_bufA);
    cudaGetSymbolAddress((void**)&bufB, g_bufB);
    cudaGetSymbolAddress((void**)&hw,   g_hw);
    cudaGetSymbolAddress((void**)&aggx, g_aggx);
    cudaGetSymbolAddress((void**)&whi,  g_Whi);
    cudaGetSymbolAddress((void**)&wlo,  g_Wlo);

    const int TB = 256;
    int gridN  = (N_NODES + TB - 1) / TB;
    int gridE  = (N_EDGES + TB - 1) / TB;
    int gridG0 = (N_NODES * (EMB / 2) + TB - 1) / TB;
    int gridAg = (N_NODES * 32 + TB - 1) / TB;
    int gridGm = (N_NODES + GBM - 1) / GBM;            // 782
    int gridW  = (3 * NKP * NPAD + TB - 1) / TB;

    // preprocessing (8 launches)
    detect_kernel<<<1, 32>>>(ei, bi);
    init_kernel<<<gridN, TB>>>();
    split_w_kernel<<<gridW, TB>>>(W1, W2, W3);
    count_kernel<<<gridE, TB>>>(ei, bi);
    scan_part_kernel<<<SCAN_NB, SCAN_B>>>();
    scan_top_kernel<<<1, 512>>>();
    scan_final_kernel<<<SCAN_NB, SCAN_B>>>();
    scatter_kernel<<<gridE, TB>>>(ei);

    const int WTOT = NKP * NPAD;

    // layer 0 (aggregate-first by linearity; bias+leaky fused into gemm0f)
    aggregate4_kernel<<<gridN, TB>>>(x, aggx);
    gemm0f_kernel<<<gridG0, TB>>>(aggx, W0, b0, bufA);

    // layer 1
    gemm_f16x2_kernel<<<gridGm, 128>>>(bufA, whi, wlo, hw);
    aggregate_h_kernel<<<gridAg, TB>>>(hw, b1, bufB);
    // layer 2
    gemm_f16x2_kernel<<<gridGm, 128>>>(bufB, whi + WTOT, wlo + WTOT, hw);
    aggregate_h_kernel<<<gridAg, TB>>>(hw, b2, bufA);
    // layer 3
    gemm_f16x2_kernel<<<gridGm, 128>>>(bufA, whi + 2 * WTOT, wlo + 2 * WTOT, hw);
    aggregate_h_kernel<<<gridAg, TB>>>(hw, b3, bufB);

    // pool + MLP head
    pool_kernel<<<N_GRAPHS, 256>>>(bufB);
    mlp_kernel<<<N_GRAPHS, HID>>>(x_scalar, Wl1, bl1, Wl2, bl2, out);
}

// round 13
// speedup vs baseline: 2.9800x; 1.0363x over previous
#include <cuda_runtime.h>
#include <cuda_fp16.h>
#include <cstdint>

#define N_NODES  50000
#define N_EDGES  400000
#define N_GRAPHS 500
#define N_FEAT   4
#define EMB      200
#define HID      128

// padded GEMM dims
#define KPAD 208            // K padded (13 chunks of 16)
#define NPAD 208            // N padded
#define NKP  (KPAD / 2)     // 104 k-pairs

// ---------------- device scratch (no runtime allocation allowed) ----------
__device__ __half g_bufA[(size_t)N_NODES * EMB];
__device__ __half g_bufB[(size_t)N_NODES * EMB];
__device__ __half g_hw  [(size_t)N_NODES * EMB];
__device__ float  g_aggx[(size_t)N_NODES * 4];
__device__ float g_dinv[N_NODES];
__device__ int   g_deg [N_NODES];
__device__ int   g_off [N_NODES + 1];
__device__ int   g_cur [N_NODES];
__device__ int2  g_csr [N_EDGES];       // {src, coef bits} packed
__device__ int   g_flag_ei;
__device__ int   g_flag_bi;
__device__ float g_pool[N_GRAPHS * EMB];
__device__ int   g_goff[N_GRAPHS + 1];  // node offsets per graph (sorted batch)
__device__ int   g_part [64];
__device__ int   g_pscan[64];
// packed fp16 hi/lo splits of W1..W3: [layer][kpair][n] as (f16 k, f16 k+1)
__device__ uint32_t g_Whi[3][NKP * NPAD];
__device__ uint32_t g_Wlo[3][NKP * NPAD];

__device__ __forceinline__ int ld_idx(const void* p, long long i, int is64) {
    if (is64) return (int)((const long long*)p)[i];
    return ((const int*)p)[i];
}

// ---------------- init + dtype detection (fused) ---------------------------
__global__ void init_kernel(const void* ei, const void* bi) {
    int i = blockIdx.x * blockDim.x + threadIdx.x;
    if (i < N_NODES) { g_deg[i] = 0; g_cur[i] = 0; }
    if (i == 0) {
        const int* e32 = (const int*)ei;
        int all0 = 1;
        for (int k = 0; k < 16; k++) if (e32[2 * k + 1] != 0) all0 = 0;
        g_flag_ei = all0;
        const int* b32 = (const int*)bi;
        int all0b = 1;
        for (int k = 0; k < 16; k++) if (b32[2 * (20000 + k) + 1] != 0) all0b = 0;
        g_flag_bi = all0b;
    }
}

// ---------------- fused: degree histogram (4 edges/thr, vectorized) --------
// + graph boundary detection on sorted batch_index (replaces atomics + scan)
__global__ void count_kernel(const void* ei, const void* bi) {
    int t = blockIdx.x * blockDim.x + threadIdx.x;
    int e0 = t * 4;
    if (e0 < N_EDGES) {
        int d0, d1, d2, d3;
        if (g_flag_ei) {
            const longlong2* p = (const longlong2*)ei + (N_EDGES + e0) / 2;
            longlong2 a = __ldg(p), b = __ldg(p + 1);
            d0 = (int)a.x; d1 = (int)a.y; d2 = (int)b.x; d3 = (int)b.y;
        } else {
            int4 a = __ldg((const int4*)((const int*)ei + N_EDGES + e0));
            d0 = a.x; d1 = a.y; d2 = a.z; d3 = a.w;
        }
        atomicAdd(&g_deg[d0], 1); atomicAdd(&g_deg[d1], 1);
        atomicAdd(&g_deg[d2], 1); atomicAdd(&g_deg[d3], 1);
    }
    int i = t;
    if (i < N_NODES) {
        int is64 = g_flag_bi;
        int b = ld_idx(bi, i, is64);
        if (i == 0) {
            for (int g = 0; g <= b; g++) g_goff[g] = 0;
        }
        if (i == N_NODES - 1) {
            for (int g = b + 1; g <= N_GRAPHS; g++) g_goff[g] = N_NODES;
        } else {
            int bn = ld_idx(bi, i + 1, is64);
            for (int g = b + 1; g <= bn; g++) g_goff[g] = i + 1;
        }
    }
}

#define SCAN_B 1024
#define SCAN_NB ((N_NODES + SCAN_B - 1) / SCAN_B)   // 49

__global__ void scan_part_kernel() {
    __shared__ int ws[32];
    int i = blockIdx.x * SCAN_B + threadIdx.x;
    int v = (i < N_NODES) ? g_deg[i] : 0;
#pragma unroll
    for (int d = 16; d; d >>= 1) v += __shfl_down_sync(0xffffffffu, v, d);
    if ((threadIdx.x & 31) == 0) ws[threadIdx.x >> 5] = v;
    __syncthreads();
    if (threadIdx.x < 32) {
        int s = ws[threadIdx.x];
#pragma unroll
        for (int d = 16; d; d >>= 1) s += __shfl_down_sync(0xffffffffu, s, d);
        if (threadIdx.x == 0) g_part[blockIdx.x] = s;
    }
}

__global__ void scan_top_kernel() {
    __shared__ int s[64];
    int t = threadIdx.x;   // 64 threads
    int v = (t < SCAN_NB) ? g_part[t] : 0;
    s[t] = v;
    __syncthreads();
    for (int d = 1; d < 64; d <<= 1) {
        int u = 0;
        if (t >= d) u = s[t - d];
        __syncthreads();
        s[t] += u;
        __syncthreads();
    }
    if (t < SCAN_NB) g_pscan[t] = s[t] - v;
    if (t == 0) g_off[N_NODES] = N_EDGES;
}

__global__ void scan_final_kernel() {
    __shared__ int wsum[32];
    int tid = threadIdx.x, lane = tid & 31, wid = tid >> 5;
    int i = blockIdx.x * SCAN_B + tid;
    int v = (i < N_NODES) ? g_deg[i] : 0;
    int inc = v;
#pragma unroll
    for (int d = 1; d < 32; d <<= 1) {
        int u = __shfl_up_sync(0xffffffffu, inc, d);
        if (lane >= d) inc += u;
    }
    if (lane == 31) wsum[wid] = inc;
    __syncthreads();
    if (wid == 0) {
        int s = wsum[lane];
        int si = s;
#pragma unroll
        for (int d = 1; d < 32; d <<= 1) {
            int u = __shfl_up_sync(0xffffffffu, si, d);
            if (lane >= d) si += u;
        }
        wsum[lane] = si - s;
    }
    __syncthreads();
    if (i < N_NODES) {
        g_off[i]  = g_pscan[blockIdx.x] + wsum[wid] + (inc - v);
        g_dinv[i] = rsqrtf((float)(v + 1));
    }
}

// 2 edges per thread, vectorized loads, packed 8B CSR stores
__global__ void scatter_kernel(const void* ei) {
    int t = blockIdx.x * blockDim.x + threadIdx.x;
    int e0 = t * 2;
    if (e0 >= N_EDGES) return;
    int s0, s1, d0, d1;
    if (g_flag_ei) {
        longlong2 sv = __ldg((const longlong2*)ei + e0 / 2);
        longlong2 dv = __ldg((const longlong2*)ei + (N_EDGES + e0) / 2);
        s0 = (int)sv.x; s1 = (int)sv.y; d0 = (int)dv.x; d1 = (int)dv.y;
    } else {
        int2 sv = __ldg((const int2*)((const int*)ei + e0));
        int2 dv = __ldg((const int2*)((const int*)ei + N_EDGES + e0));
        s0 = sv.x; s1 = sv.y; d0 = dv.x; d1 = dv.y;
    }
    int p0 = g_off[d0] + atomicAdd(&g_cur[d0], 1);
    g_csr[p0] = make_int2(s0, __float_as_int(g_dinv[s0] * g_dinv[d0]));
    int p1 = g_off[d1] + atomicAdd(&g_cur[d1], 1);
    g_csr[p1] = make_int2(s1, __float_as_int(g_dinv[s1] * g_dinv[d1]));
}

// ---------------- W split precompute (fp16 hi/lo) --------------------------
__device__ __forceinline__ uint32_t pack_h2(__half lo, __half hi) {
    uint16_t a = __half_as_ushort(lo);
    uint16_t b = __half_as_ushort(hi);
    return (uint32_t)a | ((uint32_t)b << 16);
}

__global__ void split_w_kernel(const float* __restrict__ W1,
                               const float* __restrict__ W2,
                               const float* __restrict__ W3) {
    int idx = blockIdx.x * blockDim.x + threadIdx.x;
    int total = NKP * NPAD;
    if (idx >= 3 * total) return;
    int l = idx / total;
    int r = idx - l * total;
    int kp = r / NPAD, n = r - kp * NPAD;
    const float* W = (l == 0) ? W1 : (l == 1) ? W2 : W3;
    int k0 = 2 * kp, k1 = 2 * kp + 1;
    float w0 = (k0 < EMB && n < EMB) ? W[k0 * EMB + n] : 0.f;
    float w1 = (k1 < EMB && n < EMB) ? W[k1 * EMB + n] : 0.f;
    __half h0 = __float2half_rn(w0);
    __half h1 = __float2half_rn(w1);
    __half l0 = __float2half_rn(w0 - __half2float(h0));
    __half l1 = __float2half_rn(w1 - __half2float(h1));
    g_Whi[l][r] = pack_h2(h0, h1);   // low 16 bits = even k
    g_Wlo[l][r] = pack_h2(l0, l1);
}

// ---------------- layer 0: aggregate(x) then (Ax)@W0 (linearity) -----------
__global__ void aggregate4_kernel(const float* __restrict__ x,
                                  float* __restrict__ outx) {
    int i = blockIdx.x * blockDim.x + threadIdx.x;
    if (i >= N_NODES) return;
    float dv = g_dinv[i];
    float selfc = dv * dv;
    float4 xi = *reinterpret_cast<const float4*>(x + (size_t)i * 4);
    float4 a = make_float4(selfc * xi.x, selfc * xi.y, selfc * xi.z, selfc * xi.w);
    int e0 = g_off[i], e1 = g_off[i + 1];
    for (int e = e0; e < e1; e++) {
        int2 sc = __ldg(&g_csr[e]);
        int s = sc.x;
        float c = __int_as_float(sc.y);
        float4 v = *reinterpret_cast<const float4*>(x + (size_t)s * 4);
        a.x += c * v.x; a.y += c * v.y; a.z += c * v.z; a.w += c * v.w;
    }
    *reinterpret_cast<float4*>(outx + (size_t)i * 4) = a;
}

// thread per output PAIR; writes fp16
__global__ void gemm0f_kernel(const float* __restrict__ xa,
                              const float* __restrict__ W0,
                              const float* __restrict__ b0,
                              __half* __restrict__ out) {
    int idx = blockIdx.x * blockDim.x + threadIdx.x;
    if (idx >= N_NODES * (EMB / 2)) return;
    int i = idx / (EMB / 2), p = idx - i * (EMB / 2);
    int f0 = 2 * p;
    const float* xr = xa + (size_t)i * 4;
    float x0 = xr[0], x1 = xr[1], x2 = xr[2], x3 = xr[3];
    float s0 = x0 * __ldg(&W0[f0])
             + x1 * __ldg(&W0[EMB + f0])
             + x2 * __ldg(&W0[2 * EMB + f0])
             + x3 * __ldg(&W0[3 * EMB + f0])
             + __ldg(&b0[f0]);
    float s1 = x0 * __ldg(&W0[f0 + 1])
             + x1 * __ldg(&W0[EMB + f0 + 1])
             + x2 * __ldg(&W0[2 * EMB + f0 + 1])
             + x3 * __ldg(&W0[3 * EMB + f0 + 1])
             + __ldg(&b0[f0 + 1]);
    s0 = s0 > 0.f ? s0 : 0.01f * s0;
    s1 = s1 > 0.f ? s1 : 0.01f * s1;
    __half2 o = __floats2half2_rn(s0, s1);
    *reinterpret_cast<__half2*>(&out[(size_t)i * EMB + f0]) = o;
}

// ---------------- layers 1-3: fp16x2 split GEMM via mma.sync.m16n8k16 ------
// A exact fp16 (no split); W = Whi + Wlo (fp16 pair). 2 MMAs per tile.
// block tile 64x208, 4 warps (2M x 2N), warp tile 32x104, double-buffered.
#define GBM   64
#define ASTR  12     // A smem row stride in words
#define BSTR  216    // B smem row stride in words

#define MMA_F16(d, a0, a1, a2, a3, b0, b1)                                    \
    asm volatile("mma.sync.aligned.m16n8k16.row.col.f32.f16.f16.f32 "        \
                 "{%0,%1,%2,%3}, {%4,%5,%6,%7}, {%8,%9}, {%0,%1,%2,%3};"     \
                 : "+f"((d)[0]), "+f"((d)[1]), "+f"((d)[2]), "+f"((d)[3])    \
                 : "r"(a0), "r"(a1), "r"(a2), "r"(a3), "r"(b0), "r"(b1))

__global__ __launch_bounds__(128) void gemm_f16x2_kernel(
    const __half* __restrict__ h,
    const uint32_t* __restrict__ whi, const uint32_t* __restrict__ wlo,
    __half* __restrict__ out) {
    __shared__ uint32_t sA [2][GBM * ASTR];
    __shared__ uint32_t sBh[2][8 * BSTR];
    __shared__ uint32_t sBl[2][8 * BSTR];

    int tid  = threadIdx.x;
    int lane = tid & 31, warp = tid >> 5;   // 4 warps
    int wm = warp >> 1;                     // 0..1
    int wn = warp & 1;                      // 0..1
    int row0 = blockIdx.x * GBM;
    int gid = lane >> 2;                    // 0..7
    int tig = lane & 3;                     // 0..3

    float acc[13][2][4];
#pragma unroll
    for (int t = 0; t < 13; t++)
#pragma unroll
        for (int f = 0; f < 2; f++) {
            acc[t][f][0] = 0.f; acc[t][f][1] = 0.f;
            acc[t][f][2] = 0.f; acc[t][f][3] = 0.f;
        }

    uint32_t ra[4];
    uint32_t rbh[13], rbl[13];

    auto FETCH = [&](int chunk) {
        int k0 = chunk * 16;
#pragma unroll
        for (int i = 0; i < 4; i++) {
            int idx = tid + i * 128;          // 0..511
            int r = idx >> 3, kp = idx & 7;
            int gr = row0 + r;
            int ka = k0 + 2 * kp;
            ra[i] = (gr < N_NODES && ka < EMB)
                  ? __ldg(reinterpret_cast<const uint32_t*>(h + (size_t)gr * EMB + ka))
                  : 0u;
        }
        int base = chunk * 8 * NPAD;
#pragma unroll
        for (int i = 0; i < 13; i++) {
            int idx = tid + i * 128;
            int r = idx / NPAD, c = idx - r * NPAD;
            int g = base + r * NPAD + c;
            rbh[i] = __ldg(&whi[g]);
            rbl[i] = __ldg(&wlo[g]);
        }
    };
    auto STORE = [&](int buf) {
#pragma unroll
        for (int i = 0; i < 4; i++) {
            int idx = tid + i * 128;
            int r = idx >> 3, kp = idx & 7;
            sA[buf][r * ASTR + kp] = ra[i];
        }
#pragma unroll
        for (int i = 0; i < 13; i++) {
            int idx = tid + i * 128;
            int r = idx / NPAD, c = idx - r * NPAD;
            sBh[buf][r * BSTR + c] = rbh[i];
            sBl[buf][r * BSTR + c] = rbl[i];
        }
    };

    FETCH(0);
    STORE(0);
    __syncthreads();

    int ar = wm * 32 + gid;
#pragma unroll 1
    for (int ks = 0; ks < 13; ks++) {
        int cur = ks & 1;
        if (ks < 12) FETCH(ks + 1);

        uint32_t a[8];
#pragma unroll
        for (int f = 0; f < 2; f++) {
            int r = ar + f * 16;
            a[f * 4 + 0] = sA[cur][r * ASTR + tig];
            a[f * 4 + 1] = sA[cur][(r + 8) * ASTR + tig];
            a[f * 4 + 2] = sA[cur][r * ASTR + tig + 4];
            a[f * 4 + 3] = sA[cur][(r + 8) * ASTR + tig + 4];
        }

#pragma unroll
        for (int t = 0; t < 13; t++) {
            int n = wn * 104 + t * 8 + gid;
            uint32_t bh0 = sBh[cur][tig * BSTR + n];
            uint32_t bh1 = sBh[cur][(tig + 4) * BSTR + n];
            uint32_t bl0 = sBl[cur][tig * BSTR + n];
            uint32_t bl1 = sBl[cur][(tig + 4) * BSTR + n];
            MMA_F16(acc[t][0], a[0], a[1], a[2], a[3], bh0, bh1);
            MMA_F16(acc[t][1], a[4], a[5], a[6], a[7], bh0, bh1);
            MMA_F16(acc[t][0], a[0], a[1], a[2], a[3], bl0, bl1);
            MMA_F16(acc[t][1], a[4], a[5], a[6], a[7], bl0, bl1);
        }

        if (ks < 12) STORE(cur ^ 1);
        __syncthreads();
    }

#pragma unroll
    for (int t = 0; t < 13; t++) {
        int n = wn * 104 + t * 8 + 2 * tig;
        if (n >= EMB) continue;
#pragma unroll
        for (int f = 0; f < 2; f++) {
            int r = row0 + wm * 32 + f * 16 + gid;
            if (r < N_NODES) {
                __half2 v = __floats2half2_rn(acc[t][f][0], acc[t][f][1]);
                *reinterpret_cast<__half2*>(&out[(size_t)r * EMB + n]) = v;
            }
            if (r + 8 < N_NODES) {
                __half2 v = __floats2half2_rn(acc[t][f][2], acc[t][f][3]);
                *reinterpret_cast<__half2*>(&out[(size_t)(r + 8) * EMB + n]) = v;
            }
        }
    }
}

// ---------------- edge aggregation (fp16 gather, warp per dst node) --------
// row = 200 fp16 = 400B = 25 x uint4; lanes 0..24 each own 8 features.
__device__ __forceinline__ void unpack8(uint4 v, float* f) {
    float2 t;
    t = __half22float2(*reinterpret_cast<__half2*>(&v.x)); f[0] = t.x; f[1] = t.y;
    t = __half22float2(*reinterpret_cast<__half2*>(&v.y)); f[2] = t.x; f[3] = t.y;
    t = __half22float2(*reinterpret_cast<__half2*>(&v.z)); f[4] = t.x; f[5] = t.y;
    t = __half22float2(*reinterpret_cast<__half2*>(&v.w)); f[6] = t.x; f[7] = t.y;
}

__global__ __launch_bounds__(256) void aggregate_h_kernel(
    const __half* __restrict__ hw, const float* __restrict__ b,
    __half* __restrict__ out) {
    int warp = (blockIdx.x * blockDim.x + threadIdx.x) >> 5;
    int lane = threadIdx.x & 31;
    if (warp >= N_NODES || lane >= 25) return;
    int i = warp;

    float dv = g_dinv[i];
    float selfc = dv * dv;

    const uint4* h4 = reinterpret_cast<const uint4*>(hw);
    float acc[8], f[8];
    {
        uint4 v = __ldg(&h4[(size_t)i * 25 + lane]);
        unpack8(v, f);
#pragma unroll
        for (int j = 0; j < 8; j++) acc[j] = selfc * f[j];
    }

    int e0 = g_off[i], e1 = g_off[i + 1];
    for (int e = e0; e < e1; e++) {
        int2 sc = __ldg(&g_csr[e]);
        int   s = sc.x;
        float c = __int_as_float(sc.y);
        uint4 v = __ldg(&h4[(size_t)s * 25 + lane]);
        unpack8(v, f);
#pragma unroll
        for (int j = 0; j < 8; j++) acc[j] += c * f[j];
    }

    int f0 = lane * 8;
    float4 b0 = *reinterpret_cast<const float4*>(b + f0);
    float4 b1 = *reinterpret_cast<const float4*>(b + f0 + 4);
    acc[0] += b0.x; acc[1] += b0.y; acc[2] += b0.z; acc[3] += b0.w;
    acc[4] += b1.x; acc[5] += b1.y; acc[6] += b1.z; acc[7] += b1.w;
#pragma unroll
    for (int j = 0; j < 8; j++) acc[j] = acc[j] > 0.f ? acc[j] : 0.01f * acc[j];

    uint4 pv;
    __half2 p;
    p = __floats2half2_rn(acc[0], acc[1]); pv.x = *reinterpret_cast<uint32_t*>(&p);
    p = __floats2half2_rn(acc[2], acc[3]); pv.y = *reinterpret_cast<uint32_t*>(&p);
    p = __floats2half2_rn(acc[4], acc[5]); pv.z = *reinterpret_cast<uint32_t*>(&p);
    p = __floats2half2_rn(acc[6], acc[7]); pv.w = *reinterpret_cast<uint32_t*>(&p);
    reinterpret_cast<uint4*>(out)[(size_t)i * 25 + lane] = pv;
}

// ---------------- pooling + MLP head ---------------------------------------
__global__ void pool_kernel(const __half* __restrict__ h) {
    int g = blockIdx.x;
    int t = threadIdx.x;
    if (t >= EMB) return;
    int r0 = g_goff[g];
    int n  = g_goff[g + 1] - r0;
    float s = 0.f;
    for (int j = 0; j < n; j++) s += __half2float(h[(size_t)(r0 + j) * EMB + t]);
    g_pool[g * EMB + t] = s / fmaxf((float)n, 1.0f);
}

__global__ __launch_bounds__(HID) void mlp_kernel(
    const float* __restrict__ xs,
    const float* __restrict__ Wl1, const float* __restrict__ bl1,
    const float* __restrict__ Wl2, const float* __restrict__ bl2,
    float* __restrict__ out) {
    int g = blockIdx.x;
    int t = threadIdx.x;
    __shared__ float gv[EMB + N_FEAT];
    __shared__ float red[HID];

    for (int k = t; k < EMB; k += HID) gv[k] = g_pool[g * EMB + k];
    if (t < N_FEAT) gv[EMB + t] = xs[g * N_FEAT + t];
    __syncthreads();

    float acc = bl1[t];
    for (int k = 0; k < EMB + N_FEAT; k++) acc += gv[k] * Wl1[k * HID + t];
    acc = acc > 0.f ? acc : 0.01f * acc;
    red[t] = acc * Wl2[t];
    __syncthreads();
    for (int s = HID / 2; s > 0; s >>= 1) {
        if (t < s) red[t] += red[t + s];
        __syncthreads();
    }
    if (t == 0) out[g] = red[0] + bl2[0];
}

// ---------------- launcher --------------------------------------------------
extern "C" void kernel_launch(void* const* d_in, const int* in_sizes, int n_in,
                              void* d_out, int out_size) {
    const float* x        = (const float*)d_in[0];
    const void*  ei       = d_in[1];
    const float* x_scalar = (const float*)d_in[2];
    const void*  bi       = d_in[3];
    const float* W0  = (const float*)d_in[4];
    const float* b0  = (const float*)d_in[5];
    const float* W1  = (const float*)d_in[6];
    const float* b1  = (const float*)d_in[7];
    const float* W2  = (const float*)d_in[8];
    const float* b2  = (const float*)d_in[9];
    const float* W3  = (const float*)d_in[10];
    const float* b3  = (const float*)d_in[11];
    const float* Wl1 = (const float*)d_in[12];
    const float* bl1 = (const float*)d_in[13];
    const float* Wl2 = (const float*)d_in[14];
    const float* bl2 = (const float*)d_in[15];
    float* out = (float*)d_out;

    __half *bufA, *bufB, *hw;
    float* aggx;
    uint32_t *whi, *wlo;
    cudaGetSymbolAddress((void**)&bufA, g_bufA);
    cudaGetSymbolAddress((void**)&bufB, g_bufB);
    cudaGetSymbolAddress((void**)&hw,   g_hw);
    cudaGetSymbolAddress((void**)&aggx, g_aggx);
    cudaGetSymbolAddress((void**)&whi,  g_Whi);
    cudaGetSymbolAddress((void**)&wlo,  g_Wlo);

    const int TB = 256;
    int gridN  = (N_NODES + TB - 1) / TB;
    int gridC  = (N_EDGES / 4 + TB - 1) / TB;          // 391 (covers 100096 >= 50000 nodes)
    int gridS  = (N_EDGES / 2 + TB - 1) / TB;          // 782
    int gridG0 = (N_NODES * (EMB / 2) + TB - 1) / TB;
    int gridAg = (N_NODES * 32 + TB - 1) / TB;
    int gridGm = (N_NODES + GBM - 1) / GBM;            // 782
    int gridW  = (3 * NKP * NPAD + TB - 1) / TB;

    // preprocessing (7 launches)
    init_kernel<<<gridN, TB>>>(ei, bi);
    split_w_kernel<<<gridW, TB>>>(W1, W2, W3);
    count_kernel<<<gridC, TB>>>(ei, bi);
    scan_part_kernel<<<SCAN_NB, SCAN_B>>>();
    scan_top_kernel<<<1, 64>>>();
    scan_final_kernel<<<SCAN_NB, SCAN_B>>>();
    scatter_kernel<<<gridS, TB>>>(ei);

    const int WTOT = NKP * NPAD;

    // layer 0 (aggregate-first by linearity; bias+leaky fused into gemm0f)
    aggregate4_kernel<<<gridN, TB>>>(x, aggx);
    gemm0f_kernel<<<gridG0, TB>>>(aggx, W0, b0, bufA);

    // layer 1
    gemm_f16x2_kernel<<<gridGm, 128>>>(bufA, whi, wlo, hw);
    aggregate_h_kernel<<<gridAg, TB>>>(hw, b1, bufB);
    // layer 2
    gemm_f16x2_kernel<<<gridGm, 128>>>(bufB, whi + WTOT, wlo + WTOT, hw);
    aggregate_h_kernel<<<gridAg, TB>>>(hw, b2, bufA);
    // layer 3
    gemm_f16x2_kernel<<<gridGm, 128>>>(bufA, whi + 2 * WTOT, wlo + 2 * WTOT, hw);
    aggregate_h_kernel<<<gridAg, TB>>>(hw, b3, bufB);

    // pool + MLP head
    pool_kernel<<<N_GRAPHS, 256>>>(bufB);
    mlp_kernel<<<N_GRAPHS, HID>>>(x_scalar, Wl1, bl1, Wl2, bl2, out);
}